// round 4
// baseline (speedup 1.0000x reference)
#include <cuda_runtime.h>
#include <cuda_bf16.h>
#include <cstdint>

// Problem dims (fixed by the reference)
#define BB 2
#define TT 2048
#define DD 1024
#define NN 16
#define DCONV 4
#define MROWS (BB*TT)          // 4096
#define E2 (2*DD)              // 2048
#define NPAR (2*NN+1)          // 33
#define NCH 32                 // scan chunks
#define CHL (TT/NCH)           // 64 steps per chunk

// ---------- scratch (static device allocations only) ----------
__device__ float g_xz[(size_t)MROWS * E2];        // in_proj output (x_in | z)
__device__ float g_xconv[(size_t)MROWS * DD];     // conv+silu output
__device__ float g_params[(size_t)MROWS * NPAR];  // x_proj output (B,C,dt_raw)
__device__ __nv_bfloat16 g_xhi[(size_t)MROWS * DD], g_xlo[(size_t)MROWS * DD];
__device__ __nv_bfloat16 g_w1hi[(size_t)E2 * DD],  g_w1lo[(size_t)E2 * DD];
__device__ __nv_bfloat16 g_w2hi[(size_t)DD * DD],  g_w2lo[(size_t)DD * DD];
__device__ __nv_bfloat16 g_yhi[(size_t)MROWS * DD], g_ylo[(size_t)MROWS * DD];
__device__ float g_P   [(size_t)BB * NCH * NN * DD];
__device__ float g_hend[(size_t)BB * NCH * NN * DD];
__device__ float g_hini[(size_t)BB * NCH * NN * DD];

// =====================================================================
// fp32 -> bf16 hi/lo split (vectorized)
// =====================================================================
__global__ void split_kernel(const float* __restrict__ in,
                             __nv_bfloat16* __restrict__ hi,
                             __nv_bfloat16* __restrict__ lo, int n4)
{
    int i = blockIdx.x * blockDim.x + threadIdx.x;
    if (i >= n4) return;
    float4 v = ((const float4*)in)[i];
    __nv_bfloat16 hx = __float2bfloat16_rn(v.x);
    __nv_bfloat16 hy = __float2bfloat16_rn(v.y);
    __nv_bfloat16 hz = __float2bfloat16_rn(v.z);
    __nv_bfloat16 hw = __float2bfloat16_rn(v.w);
    __nv_bfloat162 h01; h01.x = hx; h01.y = hy;
    __nv_bfloat162 h23; h23.x = hz; h23.y = hw;
    ((__nv_bfloat162*)hi)[i*2]   = h01;
    ((__nv_bfloat162*)hi)[i*2+1] = h23;
    __nv_bfloat162 l01, l23;
    l01.x = __float2bfloat16_rn(v.x - __bfloat162float(hx));
    l01.y = __float2bfloat16_rn(v.y - __bfloat162float(hy));
    l23.x = __float2bfloat16_rn(v.z - __bfloat162float(hz));
    l23.y = __float2bfloat16_rn(v.w - __bfloat162float(hw));
    ((__nv_bfloat162*)lo)[i*2]   = l01;
    ((__nv_bfloat162*)lo)[i*2+1] = l23;
}

// =====================================================================
// Tensor-core GEMM, pre-split bf16 hi/lo, cp.async double-buffered,
// SINGLE __syncthreads per k-iteration (prefetch overlaps compute).
//   C[M,N] = (Ahi+Alo)[M,K] @ (Whi+Wlo)[N,K]^T  (3-term)
// Block 128x128, BK=32, 256 threads, warp tile 64x32.
// =====================================================================
#define GLDA 40                      // bf16 elems per smem row (32 + 8 pad)
#define SM_ARR (128*GLDA)            // elems per operand array
#define SM_STAGE (4*SM_ARR)          // elems per stage (Ahi,Alo,Whi,Wlo)
#define GEMM_SMEM (2*SM_STAGE*2)     // bytes (2 stages, bf16)

__device__ __forceinline__ void mma16816(float* c, const uint32_t* a, const uint32_t* b) {
    asm volatile(
        "mma.sync.aligned.m16n8k16.row.col.f32.bf16.bf16.f32 "
        "{%0,%1,%2,%3}, {%4,%5,%6,%7}, {%8,%9}, {%0,%1,%2,%3};"
        : "+f"(c[0]), "+f"(c[1]), "+f"(c[2]), "+f"(c[3])
        : "r"(a[0]), "r"(a[1]), "r"(a[2]), "r"(a[3]), "r"(b[0]), "r"(b[1]));
}
__device__ __forceinline__ void ldm4(uint32_t* r, uint32_t addr) {
    asm volatile(
        "ldmatrix.sync.aligned.m8n8.x4.shared.b16 {%0,%1,%2,%3}, [%4];"
        : "=r"(r[0]), "=r"(r[1]), "=r"(r[2]), "=r"(r[3]) : "r"(addr));
}
__device__ __forceinline__ void cpasync16(uint32_t dst, const void* src) {
    asm volatile("cp.async.cg.shared.global [%0], [%1], 16;" :: "r"(dst), "l"(src));
}

__global__ __launch_bounds__(256) void gemm_tc_bf16(
    const __nv_bfloat16* __restrict__ Ahi, const __nv_bfloat16* __restrict__ Alo,
    const __nv_bfloat16* __restrict__ Whi, const __nv_bfloat16* __restrict__ Wlo,
    float* __restrict__ C, int M, int N, int K)
{
    extern __shared__ __align__(16) __nv_bfloat16 dsm[];

    const int tid  = threadIdx.x;
    const int lane = tid & 31;
    const int warp = tid >> 5;
    const int wm   = warp >> 2;
    const int wn   = warp & 3;
    const int brow = blockIdx.y * 128;
    const int bcol = blockIdx.x * 128;

    float acc[4][4][4];
    #pragma unroll
    for (int i = 0; i < 4; i++)
        #pragma unroll
        for (int j = 0; j < 4; j++)
            #pragma unroll
            for (int k = 0; k < 4; k++) acc[i][j][k] = 0.f;

    const uint32_t sbase = (uint32_t)__cvta_generic_to_shared(dsm);

    // cp.async mapping: per array 512 x 16B chunks (128 rows x 4); 2 per thread.
    const int ldrow = tid >> 1;
    const int ldkc0 = (tid & 1) * 2;
    const __nv_bfloat16* gA[4];
    gA[0] = Ahi + (size_t)(brow + ldrow) * K;
    gA[1] = Alo + (size_t)(brow + ldrow) * K;
    gA[2] = Whi + (size_t)(bcol + ldrow) * K;
    gA[3] = Wlo + (size_t)(bcol + ldrow) * K;

    // ldmatrix fragment offsets (bytes within one array)
    uint32_t offA[4];
    #pragma unroll
    for (int mi = 0; mi < 4; mi++) {
        int row = wm * 64 + mi * 16 + (lane & 15);
        int ko  = (lane >> 4) * 8;
        offA[mi] = (uint32_t)(row * GLDA + ko) * 2u;
    }
    uint32_t offB[2];
    #pragma unroll
    for (int ni2 = 0; ni2 < 2; ni2++) {
        int row = wn * 32 + ni2 * 16 + (lane & 7) + ((lane >> 4) << 3);
        int ko  = ((lane >> 3) & 1) * 8;
        offB[ni2] = (uint32_t)(row * GLDA + ko) * 2u;
    }

    const int NK = K / 32;

    // prologue: issue stage 0
    #pragma unroll
    for (int arr = 0; arr < 4; arr++)
        #pragma unroll
        for (int c = 0; c < 2; c++) {
            int kc = ldkc0 + c;
            uint32_t dst = sbase + (uint32_t)(arr * SM_ARR + ldrow * GLDA) * 2u + kc * 16;
            cpasync16(dst, gA[arr] + kc * 8);
        }
    asm volatile("cp.async.commit_group;");

    for (int kt = 0; kt < NK; kt++) {
        const int cur = kt & 1;

        // stage kt data ready; barrier also proves all warps finished
        // compute of iter kt-1 (which read stage (kt+1)&1) -> safe to overwrite.
        asm volatile("cp.async.wait_group 0;");
        __syncthreads();

        // prefetch stage kt+1 (overlaps the compute below)
        if (kt + 1 < NK) {
            const int nxt = (kt + 1) & 1;
            const int k0n = (kt + 1) * 32;
            #pragma unroll
            for (int arr = 0; arr < 4; arr++)
                #pragma unroll
                for (int c = 0; c < 2; c++) {
                    int kc = ldkc0 + c;
                    uint32_t dst = sbase + (uint32_t)(nxt * SM_STAGE + arr * SM_ARR + ldrow * GLDA) * 2u + kc * 16;
                    cpasync16(dst, gA[arr] + k0n + kc * 8);
                }
            asm volatile("cp.async.commit_group;");
        }

        const uint32_t stAhi = sbase + (uint32_t)(cur * SM_STAGE + 0 * SM_ARR) * 2u;
        const uint32_t stAlo = sbase + (uint32_t)(cur * SM_STAGE + 1 * SM_ARR) * 2u;
        const uint32_t stWhi = sbase + (uint32_t)(cur * SM_STAGE + 2 * SM_ARR) * 2u;
        const uint32_t stWlo = sbase + (uint32_t)(cur * SM_STAGE + 3 * SM_ARR) * 2u;

        #pragma unroll
        for (int ks = 0; ks < 2; ks++) {
            const uint32_t kadd = (uint32_t)(ks * 32);
            uint32_t ahi[4][4], alo[4][4], bhi[2][4], blo[2][4];
            #pragma unroll
            for (int ni2 = 0; ni2 < 2; ni2++) {
                ldm4(bhi[ni2], stWhi + offB[ni2] + kadd);
                ldm4(blo[ni2], stWlo + offB[ni2] + kadd);
            }
            #pragma unroll
            for (int mi = 0; mi < 4; mi++) {
                ldm4(ahi[mi], stAhi + offA[mi] + kadd);
                ldm4(alo[mi], stAlo + offA[mi] + kadd);
            }
            #pragma unroll
            for (int mi = 0; mi < 4; mi++) {
                #pragma unroll
                for (int nf = 0; nf < 4; nf++) {
                    const int ni2 = nf >> 1;
                    const int s   = (nf & 1) * 2;
                    uint32_t bh[2] = { bhi[ni2][s], bhi[ni2][s + 1] };
                    uint32_t bl[2] = { blo[ni2][s], blo[ni2][s + 1] };
                    mma16816(acc[mi][nf], ahi[mi], bh);
                    mma16816(acc[mi][nf], alo[mi], bh);
                    mma16816(acc[mi][nf], ahi[mi], bl);
                }
            }
        }
    }

    const int gid = lane >> 2;
    const int tig = lane & 3;
    #pragma unroll
    for (int mi = 0; mi < 4; mi++) {
        #pragma unroll
        for (int nf = 0; nf < 4; nf++) {
            int row = brow + wm * 64 + mi * 16 + gid;
            int col = bcol + wn * 32 + nf * 8 + tig * 2;
            *(float2*)(C + (size_t)row * N + col) =
                make_float2(acc[mi][nf][0], acc[mi][nf][1]);
            *(float2*)(C + (size_t)(row + 8) * N + col) =
                make_float2(acc[mi][nf][2], acc[mi][nf][3]);
        }
    }
}

// =====================================================================
// Depthwise causal conv (width 4) + bias + SiLU
// =====================================================================
__global__ void conv_silu_kernel(const float* __restrict__ xz,
                                 const float* __restrict__ cw,
                                 const float* __restrict__ cb,
                                 float* __restrict__ xconv)
{
    int idx = blockIdx.x * blockDim.x + threadIdx.x;
    if (idx >= MROWS * DD) return;
    int d  = idx & (DD - 1);
    int bt = idx >> 10;
    int t  = bt & (TT - 1);
    int b  = bt >> 11;

    float acc = cb[d];
    #pragma unroll
    for (int j = 0; j < DCONV; j++) {
        int tt = t - (DCONV - 1) + j;
        if (tt >= 0)
            acc = fmaf(xz[(size_t)(b * TT + tt) * E2 + d], cw[d * DCONV + j], acc);
    }
    float s = acc / (1.0f + __expf(-acc));
    xconv[(size_t)bt * DD + d] = s;
}

// =====================================================================
// Tiled x_proj: block = (33,8) threads, 32 rows per block.
// =====================================================================
__global__ void xproj_tiled(const float* __restrict__ xconv,
                            const float* __restrict__ W,
                            float* __restrict__ params)
{
    __shared__ float sx[32][68];
    const int e  = threadIdx.x;   // 0..32
    const int rg = threadIdx.y;   // 0..7
    const int flat = rg * 33 + e;
    const int row0 = blockIdx.x * 32;

    float acc[4] = {0.f, 0.f, 0.f, 0.f};

    for (int k0 = 0; k0 < DD; k0 += 64) {
        __syncthreads();
        for (int c = flat; c < 512; c += 264) {
            int ri = c >> 4;
            int k4 = c & 15;
            float4 v = *(const float4*)(xconv + (size_t)(row0 + ri) * DD + k0 + k4 * 4);
            *(float4*)&sx[ri][k4 * 4] = v;
        }
        __syncthreads();
        const float* wrow = W + (size_t)e * DD + k0;
        #pragma unroll
        for (int k4 = 0; k4 < 16; k4++) {
            float4 w4 = *(const float4*)(wrow + k4 * 4);
            #pragma unroll
            for (int j = 0; j < 4; j++) {
                const float* sxr = sx[rg * 4 + j];
                acc[j] = fmaf(sxr[k4*4+0], w4.x, acc[j]);
                acc[j] = fmaf(sxr[k4*4+1], w4.y, acc[j]);
                acc[j] = fmaf(sxr[k4*4+2], w4.z, acc[j]);
                acc[j] = fmaf(sxr[k4*4+3], w4.w, acc[j]);
            }
        }
    }
    #pragma unroll
    for (int j = 0; j < 4; j++)
        params[(size_t)(row0 + rg * 4 + j) * NPAR + e] = acc[j];
}

// =====================================================================
// Chunked scan, pass A. 128-thread blocks. Fast path: if
// a[n] == (n+1)*a[0] (A_log = log(1..N) broadcast), use ONE exp + mul
// chain per step instead of NN exps.
// grid: BB*NCH*(DD/128)
// =====================================================================
__global__ __launch_bounds__(128) void scanA_kernel(const float* __restrict__ params,
                                                    const float* __restrict__ xconv,
                                                    const float* __restrict__ dtw,
                                                    const float* __restrict__ dtb,
                                                    const float* __restrict__ A_log,
                                                    float* __restrict__ Pout,
                                                    float* __restrict__ hend)
{
    const int dg = blockIdx.x & 7;
    const int c  = (blockIdx.x >> 3) & (NCH - 1);
    const int b  = blockIdx.x >> 8;
    const int d  = dg * 128 + threadIdx.x;

    float a[NN];
    #pragma unroll
    for (int n = 0; n < NN; n++)
        a[n] = -expf(A_log[(size_t)d * NN + n]);
    const float w    = dtw[d];
    const float bias = dtb[d];

    bool fast = true;
    #pragma unroll
    for (int n = 1; n < NN; n++)
        fast = fast && (fabsf(a[n] - (float)(n + 1) * a[0]) <= 1e-4f * fabsf(a[n]) + 1e-12f);

    float h[NN], P[NN];
    #pragma unroll
    for (int n = 0; n < NN; n++) { h[n] = 0.f; P[n] = 1.f; }

    const size_t rowbase = (size_t)b * TT + (size_t)c * CHL;
    if (fast) {
        const float a0 = a[0];
        for (int t = 0; t < CHL; t++) {
            const size_t r = rowbase + t;
            const float* p = params + r * NPAR;
            float v  = fmaf(p[32], w, bias);
            float dt = (v > 20.f) ? v : __logf(1.0f + __expf(v));
            float dtx = dt * xconv[r * DD + d];
            float q = __expf(dt * a0);
            float e = q;
            #pragma unroll
            for (int n = 0; n < NN; n++) {
                h[n] = fmaf(e, h[n], dtx * p[n]);
                P[n] *= e;
                e *= q;
            }
        }
    } else {
        for (int t = 0; t < CHL; t++) {
            const size_t r = rowbase + t;
            const float* p = params + r * NPAR;
            float v  = fmaf(p[32], w, bias);
            float dt = (v > 20.f) ? v : __logf(1.0f + __expf(v));
            float dtx = dt * xconv[r * DD + d];
            #pragma unroll
            for (int n = 0; n < NN; n++) {
                float e = __expf(dt * a[n]);
                h[n] = fmaf(e, h[n], dtx * p[n]);
                P[n] *= e;
            }
        }
    }
    const size_t o = ((size_t)(b * NCH + c) * NN) * DD + d;
    #pragma unroll
    for (int n = 0; n < NN; n++) {
        hend[o + (size_t)n * DD] = h[n];
        Pout[o + (size_t)n * DD] = P[n];
    }
}

// =====================================================================
// Pass B: sequential chunk combine. thread per (b,d).
// =====================================================================
__global__ void scanB_kernel(const float* __restrict__ P,
                             const float* __restrict__ hend,
                             float* __restrict__ hini)
{
    int gid = blockIdx.x * blockDim.x + threadIdx.x;
    if (gid >= BB * DD) return;
    int d = gid & (DD - 1);
    int b = gid >> 10;

    float h[NN];
    #pragma unroll
    for (int n = 0; n < NN; n++) h[n] = 0.f;

    for (int c = 0; c < NCH; c++) {
        const size_t o = ((size_t)(b * NCH + c) * NN) * DD + d;
        #pragma unroll
        for (int n = 0; n < NN; n++) {
            hini[o + (size_t)n * DD] = h[n];
            h[n] = fmaf(P[o + (size_t)n * DD], h[n], hend[o + (size_t)n * DD]);
        }
    }
}

// =====================================================================
// Pass C: re-run chunks from h_init; emit y=(h·C)*silu(z) as bf16 hi/lo.
// =====================================================================
__global__ __launch_bounds__(128) void scanC_kernel(const float* __restrict__ params,
                                                    const float* __restrict__ xconv,
                                                    const float* __restrict__ xz,
                                                    const float* __restrict__ dtw,
                                                    const float* __restrict__ dtb,
                                                    const float* __restrict__ A_log,
                                                    const float* __restrict__ hini,
                                                    __nv_bfloat16* __restrict__ yhi,
                                                    __nv_bfloat16* __restrict__ ylo)
{
    const int dg = blockIdx.x & 7;
    const int c  = (blockIdx.x >> 3) & (NCH - 1);
    const int b  = blockIdx.x >> 8;
    const int d  = dg * 128 + threadIdx.x;

    float a[NN];
    #pragma unroll
    for (int n = 0; n < NN; n++)
        a[n] = -expf(A_log[(size_t)d * NN + n]);
    const float w    = dtw[d];
    const float bias = dtb[d];

    bool fast = true;
    #pragma unroll
    for (int n = 1; n < NN; n++)
        fast = fast && (fabsf(a[n] - (float)(n + 1) * a[0]) <= 1e-4f * fabsf(a[n]) + 1e-12f);

    float h[NN];
    const size_t o = ((size_t)(b * NCH + c) * NN) * DD + d;
    #pragma unroll
    for (int n = 0; n < NN; n++) h[n] = hini[o + (size_t)n * DD];

    const size_t rowbase = (size_t)b * TT + (size_t)c * CHL;
    if (fast) {
        const float a0 = a[0];
        for (int t = 0; t < CHL; t++) {
            const size_t r = rowbase + t;
            const float* p = params + r * NPAR;
            float v  = fmaf(p[32], w, bias);
            float dt = (v > 20.f) ? v : __logf(1.0f + __expf(v));
            float dtx = dt * xconv[r * DD + d];
            float zv  = xz[r * E2 + DD + d];
            float q = __expf(dt * a0);
            float e = q;
            float yv = 0.f;
            #pragma unroll
            for (int n = 0; n < NN; n++) {
                h[n] = fmaf(e, h[n], dtx * p[n]);
                yv = fmaf(h[n], p[NN + n], yv);
                e *= q;
            }
            float sil = zv / (1.0f + __expf(-zv));
            float val = yv * sil;
            __nv_bfloat16 hh = __float2bfloat16_rn(val);
            yhi[r * DD + d] = hh;
            ylo[r * DD + d] = __float2bfloat16_rn(val - __bfloat162float(hh));
        }
    } else {
        for (int t = 0; t < CHL; t++) {
            const size_t r = rowbase + t;
            const float* p = params + r * NPAR;
            float v  = fmaf(p[32], w, bias);
            float dt = (v > 20.f) ? v : __logf(1.0f + __expf(v));
            float dtx = dt * xconv[r * DD + d];
            float zv  = xz[r * E2 + DD + d];
            float yv = 0.f;
            #pragma unroll
            for (int n = 0; n < NN; n++) {
                float e = __expf(dt * a[n]);
                h[n] = fmaf(e, h[n], dtx * p[n]);
                yv = fmaf(h[n], p[NN + n], yv);
            }
            float sil = zv / (1.0f + __expf(-zv));
            float val = yv * sil;
            __nv_bfloat16 hh = __float2bfloat16_rn(val);
            yhi[r * DD + d] = hh;
            ylo[r * DD + d] = __float2bfloat16_rn(val - __bfloat162float(hh));
        }
    }
}

// =====================================================================
// launch
// =====================================================================
extern "C" void kernel_launch(void* const* d_in, const int* in_sizes, int n_in,
                              void* d_out, int out_size)
{
    const float* x         = (const float*)d_in[0];
    const float* in_proj_w = (const float*)d_in[1];
    const float* conv_w    = (const float*)d_in[2];
    const float* conv_b    = (const float*)d_in[3];
    const float* x_proj_w  = (const float*)d_in[4];
    const float* dt_proj_w = (const float*)d_in[5];
    const float* dt_proj_b = (const float*)d_in[6];
    const float* A_log     = (const float*)d_in[7];
    const float* out_proj_w= (const float*)d_in[8];
    float* out = (float*)d_out;

    float *xz, *xconv, *params, *P, *hend, *hini;
    __nv_bfloat16 *xhi, *xlo, *w1hi, *w1lo, *w2hi, *w2lo, *yhi, *ylo;
    cudaGetSymbolAddress((void**)&xz,     g_xz);
    cudaGetSymbolAddress((void**)&xconv,  g_xconv);
    cudaGetSymbolAddress((void**)&params, g_params);
    cudaGetSymbolAddress((void**)&P,      g_P);
    cudaGetSymbolAddress((void**)&hend,   g_hend);
    cudaGetSymbolAddress((void**)&hini,   g_hini);
    cudaGetSymbolAddress((void**)&xhi,    g_xhi);
    cudaGetSymbolAddress((void**)&xlo,    g_xlo);
    cudaGetSymbolAddress((void**)&w1hi,   g_w1hi);
    cudaGetSymbolAddress((void**)&w1lo,   g_w1lo);
    cudaGetSymbolAddress((void**)&w2hi,   g_w2hi);
    cudaGetSymbolAddress((void**)&w2lo,   g_w2lo);
    cudaGetSymbolAddress((void**)&yhi,    g_yhi);
    cudaGetSymbolAddress((void**)&ylo,    g_ylo);

    cudaFuncSetAttribute(gemm_tc_bf16,
                         cudaFuncAttributeMaxDynamicSharedMemorySize, GEMM_SMEM);

    // 0) pre-split fp32 -> bf16 hi/lo
    split_kernel<<<(MROWS*DD/4 + 255)/256, 256>>>(x, xhi, xlo, MROWS*DD/4);
    split_kernel<<<(E2*DD/4    + 255)/256, 256>>>(in_proj_w, w1hi, w1lo, E2*DD/4);
    split_kernel<<<(DD*DD/4    + 255)/256, 256>>>(out_proj_w, w2hi, w2lo, DD*DD/4);

    // 1) in_proj
    {
        dim3 grid(E2 / 128, MROWS / 128);
        gemm_tc_bf16<<<grid, 256, GEMM_SMEM>>>(xhi, xlo, w1hi, w1lo, xz, MROWS, E2, DD);
    }
    // 2) depthwise conv + SiLU
    conv_silu_kernel<<<(MROWS*DD + 255)/256, 256>>>(xz, conv_w, conv_b, xconv);
    // 3) x_proj (tiled)
    {
        dim3 blk(33, 8);
        xproj_tiled<<<MROWS / 32, blk>>>(xconv, x_proj_w, params);
    }
    // 4) chunked selective scan
    scanA_kernel<<<BB * NCH * (DD/128), 128>>>(params, xconv, dt_proj_w, dt_proj_b, A_log, P, hend);
    scanB_kernel<<<(BB*DD + 255)/256, 256>>>(P, hend, hini);
    scanC_kernel<<<BB * NCH * (DD/128), 128>>>(params, xconv, xz, dt_proj_w, dt_proj_b, A_log, hini, yhi, ylo);
    // 5) out_proj
    {
        dim3 grid(DD / 128, MROWS / 128);
        gemm_tc_bf16<<<grid, 256, GEMM_SMEM>>>(yhi, ylo, w2hi, w2lo, out, MROWS, DD, DD);
    }
}

// round 5
// speedup vs baseline: 1.0886x; 1.0886x over previous
#include <cuda_runtime.h>
#include <cuda_bf16.h>
#include <cstdint>

// Problem dims (fixed by the reference)
#define BB 2
#define TT 2048
#define DD 1024
#define NN 16
#define DCONV 4
#define MROWS (BB*TT)          // 4096
#define E2 (2*DD)              // 2048
#define NPAR (2*NN+1)          // 33
#define NCH 32                 // scan chunks
#define CHL (TT/NCH)           // 64 steps per chunk

// ---------- scratch (static device allocations only) ----------
__device__ float g_xz[(size_t)MROWS * E2];        // in_proj output (x_in | z)
__device__ float g_xconv[(size_t)MROWS * DD];     // conv+silu output
__device__ float g_params[(size_t)MROWS * NPAR];  // x_proj output (B,C,dt_raw)
__device__ __nv_bfloat16 g_xhi[(size_t)MROWS * DD], g_xlo[(size_t)MROWS * DD];
__device__ __nv_bfloat16 g_w1hi[(size_t)E2 * DD],  g_w1lo[(size_t)E2 * DD];
__device__ __nv_bfloat16 g_w2hi[(size_t)DD * DD],  g_w2lo[(size_t)DD * DD];
__device__ __nv_bfloat16 g_yhi[(size_t)MROWS * DD], g_ylo[(size_t)MROWS * DD];
__device__ float g_P   [(size_t)BB * NCH * NN * DD];
__device__ float g_hend[(size_t)BB * NCH * NN * DD];
__device__ float g_hini[(size_t)BB * NCH * NN * DD];

// =====================================================================
// fp32 -> bf16 hi/lo split (vectorized)
// =====================================================================
__global__ void split_kernel(const float* __restrict__ in,
                             __nv_bfloat16* __restrict__ hi,
                             __nv_bfloat16* __restrict__ lo, int n4)
{
    int i = blockIdx.x * blockDim.x + threadIdx.x;
    if (i >= n4) return;
    float4 v = ((const float4*)in)[i];
    __nv_bfloat16 hx = __float2bfloat16_rn(v.x);
    __nv_bfloat16 hy = __float2bfloat16_rn(v.y);
    __nv_bfloat16 hz = __float2bfloat16_rn(v.z);
    __nv_bfloat16 hw = __float2bfloat16_rn(v.w);
    __nv_bfloat162 h01; h01.x = hx; h01.y = hy;
    __nv_bfloat162 h23; h23.x = hz; h23.y = hw;
    ((__nv_bfloat162*)hi)[i*2]   = h01;
    ((__nv_bfloat162*)hi)[i*2+1] = h23;
    __nv_bfloat162 l01, l23;
    l01.x = __float2bfloat16_rn(v.x - __bfloat162float(hx));
    l01.y = __float2bfloat16_rn(v.y - __bfloat162float(hy));
    l23.x = __float2bfloat16_rn(v.z - __bfloat162float(hz));
    l23.y = __float2bfloat16_rn(v.w - __bfloat162float(hw));
    ((__nv_bfloat162*)lo)[i*2]   = l01;
    ((__nv_bfloat162*)lo)[i*2+1] = l23;
}

// =====================================================================
// Tensor-core GEMM, pre-split bf16 hi/lo, cp.async double-buffered,
// single __syncthreads per k-iter, __launch_bounds__(256,2) caps regs
// at 128 so TWO blocks co-reside per SM (RF = 64K regs).
//   C[M,N] = (Ahi+Alo)[M,K] @ (Whi+Wlo)[N,K]^T  (3-term)
// Block 128x128, BK=32, 256 threads, warp tile 64x32.
// =====================================================================
#define GLDA 40                      // bf16 elems per smem row (32 + 8 pad)
#define SM_ARR (128*GLDA)            // elems per operand array
#define SM_STAGE (4*SM_ARR)          // elems per stage (Ahi,Alo,Whi,Wlo)
#define GEMM_SMEM (2*SM_STAGE*2)     // bytes (2 stages, bf16) = 81920

__device__ __forceinline__ void mma16816(float* c, const uint32_t* a, const uint32_t* b) {
    asm volatile(
        "mma.sync.aligned.m16n8k16.row.col.f32.bf16.bf16.f32 "
        "{%0,%1,%2,%3}, {%4,%5,%6,%7}, {%8,%9}, {%0,%1,%2,%3};"
        : "+f"(c[0]), "+f"(c[1]), "+f"(c[2]), "+f"(c[3])
        : "r"(a[0]), "r"(a[1]), "r"(a[2]), "r"(a[3]), "r"(b[0]), "r"(b[1]));
}
__device__ __forceinline__ void ldm4(uint32_t* r, uint32_t addr) {
    asm volatile(
        "ldmatrix.sync.aligned.m8n8.x4.shared.b16 {%0,%1,%2,%3}, [%4];"
        : "=r"(r[0]), "=r"(r[1]), "=r"(r[2]), "=r"(r[3]) : "r"(addr));
}
__device__ __forceinline__ void cpasync16(uint32_t dst, const void* src) {
    asm volatile("cp.async.cg.shared.global [%0], [%1], 16;" :: "r"(dst), "l"(src));
}

__global__ __launch_bounds__(256, 2) void gemm_tc_bf16(
    const __nv_bfloat16* __restrict__ Ahi, const __nv_bfloat16* __restrict__ Alo,
    const __nv_bfloat16* __restrict__ Whi, const __nv_bfloat16* __restrict__ Wlo,
    float* __restrict__ C, int M, int N, int K)
{
    extern __shared__ __align__(16) __nv_bfloat16 dsm[];

    const int tid  = threadIdx.x;
    const int lane = tid & 31;
    const int warp = tid >> 5;
    const int wm   = warp >> 2;
    const int wn   = warp & 3;
    const int brow = blockIdx.y * 128;
    const int bcol = blockIdx.x * 128;

    float acc[4][4][4];
    #pragma unroll
    for (int i = 0; i < 4; i++)
        #pragma unroll
        for (int j = 0; j < 4; j++)
            #pragma unroll
            for (int k = 0; k < 4; k++) acc[i][j][k] = 0.f;

    const uint32_t sbase = (uint32_t)__cvta_generic_to_shared(dsm);

    // cp.async mapping: per array 512 x 16B chunks (128 rows x 4); 2 per thread.
    const int ldrow = tid >> 1;
    const int ldkc0 = (tid & 1) * 2;
    const __nv_bfloat16* gA[4];
    gA[0] = Ahi + (size_t)(brow + ldrow) * K;
    gA[1] = Alo + (size_t)(brow + ldrow) * K;
    gA[2] = Whi + (size_t)(bcol + ldrow) * K;
    gA[3] = Wlo + (size_t)(bcol + ldrow) * K;

    // ldmatrix fragment offsets (bytes within one array)
    uint32_t offA[4];
    #pragma unroll
    for (int mi = 0; mi < 4; mi++) {
        int row = wm * 64 + mi * 16 + (lane & 15);
        int ko  = (lane >> 4) * 8;
        offA[mi] = (uint32_t)(row * GLDA + ko) * 2u;
    }
    uint32_t offB[2];
    #pragma unroll
    for (int ni2 = 0; ni2 < 2; ni2++) {
        int row = wn * 32 + ni2 * 16 + (lane & 7) + ((lane >> 4) << 3);
        int ko  = ((lane >> 3) & 1) * 8;
        offB[ni2] = (uint32_t)(row * GLDA + ko) * 2u;
    }

    const int NK = K / 32;

    // prologue: issue stage 0
    #pragma unroll
    for (int arr = 0; arr < 4; arr++)
        #pragma unroll
        for (int c = 0; c < 2; c++) {
            int kc = ldkc0 + c;
            uint32_t dst = sbase + (uint32_t)(arr * SM_ARR + ldrow * GLDA) * 2u + kc * 16;
            cpasync16(dst, gA[arr] + kc * 8);
        }
    asm volatile("cp.async.commit_group;");

    for (int kt = 0; kt < NK; kt++) {
        const int cur = kt & 1;

        // stage kt ready; barrier also proves every warp finished the
        // previous iter's compute -> safe to overwrite the other stage.
        asm volatile("cp.async.wait_group 0;");
        __syncthreads();

        // prefetch stage kt+1 (overlaps the compute below)
        if (kt + 1 < NK) {
            const int nxt = (kt + 1) & 1;
            const int k0n = (kt + 1) * 32;
            #pragma unroll
            for (int arr = 0; arr < 4; arr++)
                #pragma unroll
                for (int c = 0; c < 2; c++) {
                    int kc = ldkc0 + c;
                    uint32_t dst = sbase + (uint32_t)(nxt * SM_STAGE + arr * SM_ARR + ldrow * GLDA) * 2u + kc * 16;
                    cpasync16(dst, gA[arr] + k0n + kc * 8);
                }
            asm volatile("cp.async.commit_group;");
        }

        const uint32_t stAhi = sbase + (uint32_t)(cur * SM_STAGE + 0 * SM_ARR) * 2u;
        const uint32_t stAlo = sbase + (uint32_t)(cur * SM_STAGE + 1 * SM_ARR) * 2u;
        const uint32_t stWhi = sbase + (uint32_t)(cur * SM_STAGE + 2 * SM_ARR) * 2u;
        const uint32_t stWlo = sbase + (uint32_t)(cur * SM_STAGE + 3 * SM_ARR) * 2u;

        #pragma unroll
        for (int ks = 0; ks < 2; ks++) {
            const uint32_t kadd = (uint32_t)(ks * 32);
            uint32_t ahi[4][4], alo[4][4], bhi[2][4], blo[2][4];
            #pragma unroll
            for (int ni2 = 0; ni2 < 2; ni2++) {
                ldm4(bhi[ni2], stWhi + offB[ni2] + kadd);
                ldm4(blo[ni2], stWlo + offB[ni2] + kadd);
            }
            #pragma unroll
            for (int mi = 0; mi < 4; mi++) {
                ldm4(ahi[mi], stAhi + offA[mi] + kadd);
                ldm4(alo[mi], stAlo + offA[mi] + kadd);
            }
            #pragma unroll
            for (int mi = 0; mi < 4; mi++) {
                #pragma unroll
                for (int nf = 0; nf < 4; nf++) {
                    const int ni2 = nf >> 1;
                    const int s   = (nf & 1) * 2;
                    uint32_t bh[2] = { bhi[ni2][s], bhi[ni2][s + 1] };
                    uint32_t bl[2] = { blo[ni2][s], blo[ni2][s + 1] };
                    mma16816(acc[mi][nf], ahi[mi], bh);
                    mma16816(acc[mi][nf], alo[mi], bh);
                    mma16816(acc[mi][nf], ahi[mi], bl);
                }
            }
        }
    }

    const int gid = lane >> 2;
    const int tig = lane & 3;
    #pragma unroll
    for (int mi = 0; mi < 4; mi++) {
        #pragma unroll
        for (int nf = 0; nf < 4; nf++) {
            int row = brow + wm * 64 + mi * 16 + gid;
            int col = bcol + wn * 32 + nf * 8 + tig * 2;
            *(float2*)(C + (size_t)row * N + col) =
                make_float2(acc[mi][nf][0], acc[mi][nf][1]);
            *(float2*)(C + (size_t)(row + 8) * N + col) =
                make_float2(acc[mi][nf][2], acc[mi][nf][3]);
        }
    }
}

// =====================================================================
// Depthwise causal conv (width 4) + bias + SiLU
// =====================================================================
__global__ void conv_silu_kernel(const float* __restrict__ xz,
                                 const float* __restrict__ cw,
                                 const float* __restrict__ cb,
                                 float* __restrict__ xconv)
{
    int idx = blockIdx.x * blockDim.x + threadIdx.x;
    if (idx >= MROWS * DD) return;
    int d  = idx & (DD - 1);
    int bt = idx >> 10;
    int t  = bt & (TT - 1);
    int b  = bt >> 11;

    float acc = cb[d];
    #pragma unroll
    for (int j = 0; j < DCONV; j++) {
        int tt = t - (DCONV - 1) + j;
        if (tt >= 0)
            acc = fmaf(xz[(size_t)(b * TT + tt) * E2 + d], cw[d * DCONV + j], acc);
    }
    float s = acc / (1.0f + __expf(-acc));
    xconv[(size_t)bt * DD + d] = s;
}

// =====================================================================
// Tiled x_proj: block = (33,8) threads, 32 rows per block.
// =====================================================================
__global__ void xproj_tiled(const float* __restrict__ xconv,
                            const float* __restrict__ W,
                            float* __restrict__ params)
{
    __shared__ float sx[32][68];
    const int e  = threadIdx.x;   // 0..32
    const int rg = threadIdx.y;   // 0..7
    const int flat = rg * 33 + e;
    const int row0 = blockIdx.x * 32;

    float acc[4] = {0.f, 0.f, 0.f, 0.f};

    for (int k0 = 0; k0 < DD; k0 += 64) {
        __syncthreads();
        for (int c = flat; c < 512; c += 264) {
            int ri = c >> 4;
            int k4 = c & 15;
            float4 v = *(const float4*)(xconv + (size_t)(row0 + ri) * DD + k0 + k4 * 4);
            *(float4*)&sx[ri][k4 * 4] = v;
        }
        __syncthreads();
        const float* wrow = W + (size_t)e * DD + k0;
        #pragma unroll
        for (int k4 = 0; k4 < 16; k4++) {
            float4 w4 = *(const float4*)(wrow + k4 * 4);
            #pragma unroll
            for (int j = 0; j < 4; j++) {
                const float* sxr = sx[rg * 4 + j];
                acc[j] = fmaf(sxr[k4*4+0], w4.x, acc[j]);
                acc[j] = fmaf(sxr[k4*4+1], w4.y, acc[j]);
                acc[j] = fmaf(sxr[k4*4+2], w4.z, acc[j]);
                acc[j] = fmaf(sxr[k4*4+3], w4.w, acc[j]);
            }
        }
    }
    #pragma unroll
    for (int j = 0; j < 4; j++)
        params[(size_t)(row0 + rg * 4 + j) * NPAR + e] = acc[j];
}

// =====================================================================
// Chunked scan, pass A. 128-thread blocks. Fast path: if
// a[n] == (n+1)*a[0] (A_log = log(1..N) broadcast), use ONE exp + mul
// chain per step instead of NN exps.
// =====================================================================
__global__ __launch_bounds__(128) void scanA_kernel(const float* __restrict__ params,
                                                    const float* __restrict__ xconv,
                                                    const float* __restrict__ dtw,
                                                    const float* __restrict__ dtb,
                                                    const float* __restrict__ A_log,
                                                    float* __restrict__ Pout,
                                                    float* __restrict__ hend)
{
    const int dg = blockIdx.x & 7;
    const int c  = (blockIdx.x >> 3) & (NCH - 1);
    const int b  = blockIdx.x >> 8;
    const int d  = dg * 128 + threadIdx.x;

    float a[NN];
    #pragma unroll
    for (int n = 0; n < NN; n++)
        a[n] = -expf(A_log[(size_t)d * NN + n]);
    const float w    = dtw[d];
    const float bias = dtb[d];

    bool fast = true;
    #pragma unroll
    for (int n = 1; n < NN; n++)
        fast = fast && (fabsf(a[n] - (float)(n + 1) * a[0]) <= 1e-4f * fabsf(a[n]) + 1e-12f);

    float h[NN], P[NN];
    #pragma unroll
    for (int n = 0; n < NN; n++) { h[n] = 0.f; P[n] = 1.f; }

    const size_t rowbase = (size_t)b * TT + (size_t)c * CHL;
    if (fast) {
        const float a0 = a[0];
        for (int t = 0; t < CHL; t++) {
            const size_t r = rowbase + t;
            const float* p = params + r * NPAR;
            float v  = fmaf(p[32], w, bias);
            float dt = (v > 20.f) ? v : __logf(1.0f + __expf(v));
            float dtx = dt * xconv[r * DD + d];
            float q = __expf(dt * a0);
            float e = q;
            #pragma unroll
            for (int n = 0; n < NN; n++) {
                h[n] = fmaf(e, h[n], dtx * p[n]);
                P[n] *= e;
                e *= q;
            }
        }
    } else {
        for (int t = 0; t < CHL; t++) {
            const size_t r = rowbase + t;
            const float* p = params + r * NPAR;
            float v  = fmaf(p[32], w, bias);
            float dt = (v > 20.f) ? v : __logf(1.0f + __expf(v));
            float dtx = dt * xconv[r * DD + d];
            #pragma unroll
            for (int n = 0; n < NN; n++) {
                float e = __expf(dt * a[n]);
                h[n] = fmaf(e, h[n], dtx * p[n]);
                P[n] *= e;
            }
        }
    }
    const size_t o = ((size_t)(b * NCH + c) * NN) * DD + d;
    #pragma unroll
    for (int n = 0; n < NN; n++) {
        hend[o + (size_t)n * DD] = h[n];
        Pout[o + (size_t)n * DD] = P[n];
    }
}

// =====================================================================
// Pass B: sequential chunk combine. thread per (b,d).
// =====================================================================
__global__ void scanB_kernel(const float* __restrict__ P,
                             const float* __restrict__ hend,
                             float* __restrict__ hini)
{
    int gid = blockIdx.x * blockDim.x + threadIdx.x;
    if (gid >= BB * DD) return;
    int d = gid & (DD - 1);
    int b = gid >> 10;

    float h[NN];
    #pragma unroll
    for (int n = 0; n < NN; n++) h[n] = 0.f;

    for (int c = 0; c < NCH; c++) {
        const size_t o = ((size_t)(b * NCH + c) * NN) * DD + d;
        #pragma unroll
        for (int n = 0; n < NN; n++) {
            hini[o + (size_t)n * DD] = h[n];
            h[n] = fmaf(P[o + (size_t)n * DD], h[n], hend[o + (size_t)n * DD]);
        }
    }
}

// =====================================================================
// Pass C: re-run chunks from h_init; emit y=(h·C)*silu(z) as bf16 hi/lo.
// =====================================================================
__global__ __launch_bounds__(128) void scanC_kernel(const float* __restrict__ params,
                                                    const float* __restrict__ xconv,
                                                    const float* __restrict__ xz,
                                                    const float* __restrict__ dtw,
                                                    const float* __restrict__ dtb,
                                                    const float* __restrict__ A_log,
                                                    const float* __restrict__ hini,
                                                    __nv_bfloat16* __restrict__ yhi,
                                                    __nv_bfloat16* __restrict__ ylo)
{
    const int dg = blockIdx.x & 7;
    const int c  = (blockIdx.x >> 3) & (NCH - 1);
    const int b  = blockIdx.x >> 8;
    const int d  = dg * 128 + threadIdx.x;

    float a[NN];
    #pragma unroll
    for (int n = 0; n < NN; n++)
        a[n] = -expf(A_log[(size_t)d * NN + n]);
    const float w    = dtw[d];
    const float bias = dtb[d];

    bool fast = true;
    #pragma unroll
    for (int n = 1; n < NN; n++)
        fast = fast && (fabsf(a[n] - (float)(n + 1) * a[0]) <= 1e-4f * fabsf(a[n]) + 1e-12f);

    float h[NN];
    const size_t o = ((size_t)(b * NCH + c) * NN) * DD + d;
    #pragma unroll
    for (int n = 0; n < NN; n++) h[n] = hini[o + (size_t)n * DD];

    const size_t rowbase = (size_t)b * TT + (size_t)c * CHL;
    if (fast) {
        const float a0 = a[0];
        for (int t = 0; t < CHL; t++) {
            const size_t r = rowbase + t;
            const float* p = params + r * NPAR;
            float v  = fmaf(p[32], w, bias);
            float dt = (v > 20.f) ? v : __logf(1.0f + __expf(v));
            float dtx = dt * xconv[r * DD + d];
            float zv  = xz[r * E2 + DD + d];
            float q = __expf(dt * a0);
            float e = q;
            float yv = 0.f;
            #pragma unroll
            for (int n = 0; n < NN; n++) {
                h[n] = fmaf(e, h[n], dtx * p[n]);
                yv = fmaf(h[n], p[NN + n], yv);
                e *= q;
            }
            float sil = zv / (1.0f + __expf(-zv));
            float val = yv * sil;
            __nv_bfloat16 hh = __float2bfloat16_rn(val);
            yhi[r * DD + d] = hh;
            ylo[r * DD + d] = __float2bfloat16_rn(val - __bfloat162float(hh));
        }
    } else {
        for (int t = 0; t < CHL; t++) {
            const size_t r = rowbase + t;
            const float* p = params + r * NPAR;
            float v  = fmaf(p[32], w, bias);
            float dt = (v > 20.f) ? v : __logf(1.0f + __expf(v));
            float dtx = dt * xconv[r * DD + d];
            float zv  = xz[r * E2 + DD + d];
            float yv = 0.f;
            #pragma unroll
            for (int n = 0; n < NN; n++) {
                float e = __expf(dt * a[n]);
                h[n] = fmaf(e, h[n], dtx * p[n]);
                yv = fmaf(h[n], p[NN + n], yv);
            }
            float sil = zv / (1.0f + __expf(-zv));
            float val = yv * sil;
            __nv_bfloat16 hh = __float2bfloat16_rn(val);
            yhi[r * DD + d] = hh;
            ylo[r * DD + d] = __float2bfloat16_rn(val - __bfloat162float(hh));
        }
    }
}

// =====================================================================
// launch
// =====================================================================
extern "C" void kernel_launch(void* const* d_in, const int* in_sizes, int n_in,
                              void* d_out, int out_size)
{
    const float* x         = (const float*)d_in[0];
    const float* in_proj_w = (const float*)d_in[1];
    const float* conv_w    = (const float*)d_in[2];
    const float* conv_b    = (const float*)d_in[3];
    const float* x_proj_w  = (const float*)d_in[4];
    const float* dt_proj_w = (const float*)d_in[5];
    const float* dt_proj_b = (const float*)d_in[6];
    const float* A_log     = (const float*)d_in[7];
    const float* out_proj_w= (const float*)d_in[8];
    float* out = (float*)d_out;

    float *xz, *xconv, *params, *P, *hend, *hini;
    __nv_bfloat16 *xhi, *xlo, *w1hi, *w1lo, *w2hi, *w2lo, *yhi, *ylo;
    cudaGetSymbolAddress((void**)&xz,     g_xz);
    cudaGetSymbolAddress((void**)&xconv,  g_xconv);
    cudaGetSymbolAddress((void**)&params, g_params);
    cudaGetSymbolAddress((void**)&P,      g_P);
    cudaGetSymbolAddress((void**)&hend,   g_hend);
    cudaGetSymbolAddress((void**)&hini,   g_hini);
    cudaGetSymbolAddress((void**)&xhi,    g_xhi);
    cudaGetSymbolAddress((void**)&xlo,    g_xlo);
    cudaGetSymbolAddress((void**)&w1hi,   g_w1hi);
    cudaGetSymbolAddress((void**)&w1lo,   g_w1lo);
    cudaGetSymbolAddress((void**)&w2hi,   g_w2hi);
    cudaGetSymbolAddress((void**)&w2lo,   g_w2lo);
    cudaGetSymbolAddress((void**)&yhi,    g_yhi);
    cudaGetSymbolAddress((void**)&ylo,    g_ylo);

    cudaFuncSetAttribute(gemm_tc_bf16,
                         cudaFuncAttributeMaxDynamicSharedMemorySize, GEMM_SMEM);

    // 0) pre-split fp32 -> bf16 hi/lo
    split_kernel<<<(MROWS*DD/4 + 255)/256, 256>>>(x, xhi, xlo, MROWS*DD/4);
    split_kernel<<<(E2*DD/4    + 255)/256, 256>>>(in_proj_w, w1hi, w1lo, E2*DD/4);
    split_kernel<<<(DD*DD/4    + 255)/256, 256>>>(out_proj_w, w2hi, w2lo, DD*DD/4);

    // 1) in_proj
    {
        dim3 grid(E2 / 128, MROWS / 128);
        gemm_tc_bf16<<<grid, 256, GEMM_SMEM>>>(xhi, xlo, w1hi, w1lo, xz, MROWS, E2, DD);
    }
    // 2) depthwise conv + SiLU
    conv_silu_kernel<<<(MROWS*DD + 255)/256, 256>>>(xz, conv_w, conv_b, xconv);
    // 3) x_proj (tiled)
    {
        dim3 blk(33, 8);
        xproj_tiled<<<MROWS / 32, blk>>>(xconv, x_proj_w, params);
    }
    // 4) chunked selective scan
    scanA_kernel<<<BB * NCH * (DD/128), 128>>>(params, xconv, dt_proj_w, dt_proj_b, A_log, P, hend);
    scanB_kernel<<<(BB*DD + 255)/256, 256>>>(P, hend, hini);
    scanC_kernel<<<BB * NCH * (DD/128), 128>>>(params, xconv, xz, dt_proj_w, dt_proj_b, A_log, hini, yhi, ylo);
    // 5) out_proj
    {
        dim3 grid(DD / 128, MROWS / 128);
        gemm_tc_bf16<<<grid, 256, GEMM_SMEM>>>(yhi, ylo, w2hi, w2lo, out, MROWS, DD, DD);
    }
}

// round 7
// speedup vs baseline: 1.3497x; 1.2398x over previous
#include <cuda_runtime.h>
#include <cuda_fp16.h>
#include <cstdint>

// Problem dims (fixed by the reference)
#define BB 2
#define TT 2048
#define DD 1024
#define NN 16
#define DCONV 4
#define MROWS (BB*TT)          // 4096
#define E2 (2*DD)              // 2048
#define NPAR (2*NN+1)          // 33
#define NCH 32                 // scan chunks
#define CHL (TT/NCH)           // 64 steps per chunk

// ---------- scratch (static device allocations only) ----------
__device__ float g_xz[(size_t)MROWS * E2];        // in_proj output (x_in | z)
__device__ float g_xconv[(size_t)MROWS * DD];     // conv+silu output
__device__ float g_params[(size_t)MROWS * NPAR];  // x_proj output (B,C,dt_raw)
__device__ __half g_xh [(size_t)MROWS * DD];      // x in fp16
__device__ __half g_w1hi[(size_t)E2 * DD], g_w1lo[(size_t)E2 * DD];
__device__ __half g_w2hi[(size_t)DD * DD], g_w2lo[(size_t)DD * DD];
__device__ __half g_yh [(size_t)MROWS * DD];      // scan output in fp16
__device__ float g_P   [(size_t)BB * NCH * NN * DD];
__device__ float g_hend[(size_t)BB * NCH * NN * DD];
__device__ float g_hini[(size_t)BB * NCH * NN * DD];

// =====================================================================
// fp32 -> fp16 convert (A side, single term)
// =====================================================================
__global__ void tohalf_kernel(const float* __restrict__ in,
                              __half* __restrict__ out, int n4)
{
    int i = blockIdx.x * blockDim.x + threadIdx.x;
    if (i >= n4) return;
    float4 v = ((const float4*)in)[i];
    ((__half2*)out)[i*2]   = __floats2half2_rn(v.x, v.y);
    ((__half2*)out)[i*2+1] = __floats2half2_rn(v.z, v.w);
}

// =====================================================================
// fp32 -> fp16 hi/lo split (W side, 22-bit effective)
// =====================================================================
__global__ void splitw_kernel(const float* __restrict__ in,
                              __half* __restrict__ hi,
                              __half* __restrict__ lo, int n4)
{
    int i = blockIdx.x * blockDim.x + threadIdx.x;
    if (i >= n4) return;
    float4 v = ((const float4*)in)[i];
    __half hx = __float2half_rn(v.x);
    __half hy = __float2half_rn(v.y);
    __half hz = __float2half_rn(v.z);
    __half hw = __float2half_rn(v.w);
    __half2 h01; h01.x = hx; h01.y = hy;
    __half2 h23; h23.x = hz; h23.y = hw;
    ((__half2*)hi)[i*2]   = h01;
    ((__half2*)hi)[i*2+1] = h23;
    __half2 l01, l23;
    l01.x = __float2half_rn(v.x - __half2float(hx));
    l01.y = __float2half_rn(v.y - __half2float(hy));
    l23.x = __float2half_rn(v.z - __half2float(hz));
    l23.y = __float2half_rn(v.w - __half2float(hw));
    ((__half2*)lo)[i*2]   = l01;
    ((__half2*)lo)[i*2+1] = l23;
}

// =====================================================================
// Tensor-core GEMM, fp16 2-term: C[M,N] = A16[M,K] @ (Whi+Wlo)[N,K]^T
// Block 128x128, BK=32, 256 threads (8 warps), warp tile 64x32,
// 3-stage cp.async pipeline, single __syncthreads per k-iter,
// __launch_bounds__(256,2) -> 2 blocks/SM.
// =====================================================================
#define GLDA 40                       // half elems per smem row (32 + 8 pad)
#define ARR_B  (128*GLDA*2)           // bytes per operand array = 10240
#define STAGE_B (3*ARR_B)             // A, Whi, Wlo = 30720
#define NSTAGE 3
#define GEMM_SMEM (NSTAGE*STAGE_B)    // 92160 bytes

__device__ __forceinline__ void mma16816h(float* c, const uint32_t* a, const uint32_t* b) {
    asm volatile(
        "mma.sync.aligned.m16n8k16.row.col.f32.f16.f16.f32 "
        "{%0,%1,%2,%3}, {%4,%5,%6,%7}, {%8,%9}, {%0,%1,%2,%3};"
        : "+f"(c[0]), "+f"(c[1]), "+f"(c[2]), "+f"(c[3])
        : "r"(a[0]), "r"(a[1]), "r"(a[2]), "r"(a[3]), "r"(b[0]), "r"(b[1]));
}
__device__ __forceinline__ void ldm4(uint32_t* r, uint32_t addr) {
    asm volatile(
        "ldmatrix.sync.aligned.m8n8.x4.shared.b16 {%0,%1,%2,%3}, [%4];"
        : "=r"(r[0]), "=r"(r[1]), "=r"(r[2]), "=r"(r[3]) : "r"(addr));
}
__device__ __forceinline__ void cpasync16(uint32_t dst, const void* src) {
    asm volatile("cp.async.cg.shared.global [%0], [%1], 16;" :: "r"(dst), "l"(src));
}

__global__ __launch_bounds__(256, 2) void gemm_fp16_2t(
    const __half* __restrict__ A,
    const __half* __restrict__ Whi, const __half* __restrict__ Wlo,
    float* __restrict__ C, int M, int N, int K)
{
    extern __shared__ __align__(16) char dsm[];

    const int tid  = threadIdx.x;
    const int lane = tid & 31;
    const int warp = tid >> 5;
    const int wm   = warp >> 2;          // 0..1
    const int wn   = warp & 3;           // 0..3
    const int brow = blockIdx.y * 128;
    const int bcol = blockIdx.x * 128;

    float acc[4][4][4];
    #pragma unroll
    for (int i = 0; i < 4; i++)
        #pragma unroll
        for (int j = 0; j < 4; j++)
            #pragma unroll
            for (int k = 0; k < 4; k++) acc[i][j][k] = 0.f;

    const uint32_t sbase = (uint32_t)__cvta_generic_to_shared(dsm);

    const __half* srcs[3];
    srcs[0] = A   + (size_t)(brow) * K;
    srcs[1] = Whi + (size_t)(bcol) * K;
    srcs[2] = Wlo + (size_t)(bcol) * K;

    // ldmatrix fragment offsets (bytes within one array)
    uint32_t offA[4];
    #pragma unroll
    for (int mi = 0; mi < 4; mi++) {
        int row = wm * 64 + mi * 16 + (lane & 15);
        int ko  = (lane >> 4) * 8;
        offA[mi] = (uint32_t)(row * GLDA + ko) * 2u;
    }
    uint32_t offB[2];
    #pragma unroll
    for (int ni2 = 0; ni2 < 2; ni2++) {
        int row = wn * 32 + ni2 * 16 + (lane & 7) + ((lane >> 4) << 3);
        int ko  = ((lane >> 3) & 1) * 8;
        offB[ni2] = (uint32_t)(row * GLDA + ko) * 2u;
    }

    const int NK = K / 32;

    // loader: one 128x32 slab of 3 arrays into a stage.
    // 3 arrays x 512 chunks(16B) = 1536 chunks; 256 threads x 6.
    auto load_slab = [&](int slab, int stage) {
        const uint32_t stB = sbase + (uint32_t)stage * STAGE_B;
        #pragma unroll
        for (int arr = 0; arr < 3; arr++) {
            const __half* sp = srcs[arr] + slab * 32;
            #pragma unroll
            for (int j = 0; j < 2; j++) {
                int idx = tid + j * 256;       // 0..511
                int row = idx >> 2;
                int kc  = idx & 3;
                uint32_t dst = stB + (uint32_t)arr * ARR_B + (uint32_t)(row * GLDA + kc * 8) * 2u;
                cpasync16(dst, sp + (size_t)row * K + kc * 8);
            }
        }
        asm volatile("cp.async.commit_group;");
    };

    load_slab(0, 0);
    load_slab(1, 1);

    for (int kt = 0; kt < NK; kt++) {
        const int stage = kt % 3;
        if (kt < NK - 1) asm volatile("cp.async.wait_group 1;");
        else             asm volatile("cp.async.wait_group 0;");
        __syncthreads();   // slab kt ready; all warps done with iter kt-1

        // prefetch slab kt+2 into stage (kt+2)%3 (free since iter kt-1 done)
        if (kt + 2 < NK) load_slab(kt + 2, (kt + 2) % 3);

        const uint32_t stA   = sbase + (uint32_t)stage * STAGE_B;
        const uint32_t stWhi = stA + ARR_B;
        const uint32_t stWlo = stA + 2 * ARR_B;

        #pragma unroll
        for (int ks = 0; ks < 2; ks++) {
            const uint32_t kadd = (uint32_t)(ks * 32);   // 16 half = 32B
            uint32_t a[4][4], bhi[2][4], blo[2][4];
            #pragma unroll
            for (int ni2 = 0; ni2 < 2; ni2++) {
                ldm4(bhi[ni2], stWhi + offB[ni2] + kadd);
                ldm4(blo[ni2], stWlo + offB[ni2] + kadd);
            }
            #pragma unroll
            for (int mi = 0; mi < 4; mi++)
                ldm4(a[mi], stA + offA[mi] + kadd);
            #pragma unroll
            for (int mi = 0; mi < 4; mi++) {
                #pragma unroll
                for (int nf = 0; nf < 4; nf++) {
                    const int ni2 = nf >> 1;
                    const int s   = (nf & 1) * 2;
                    uint32_t bh[2] = { bhi[ni2][s], bhi[ni2][s + 1] };
                    uint32_t bl[2] = { blo[ni2][s], blo[ni2][s + 1] };
                    mma16816h(acc[mi][nf], a[mi], bh);
                    mma16816h(acc[mi][nf], a[mi], bl);
                }
            }
        }
    }

    const int gid = lane >> 2;
    const int tig = lane & 3;
    #pragma unroll
    for (int mi = 0; mi < 4; mi++) {
        #pragma unroll
        for (int nf = 0; nf < 4; nf++) {
            int row = brow + wm * 64 + mi * 16 + gid;
            int col = bcol + wn * 32 + nf * 8 + tig * 2;
            *(float2*)(C + (size_t)row * N + col) =
                make_float2(acc[mi][nf][0], acc[mi][nf][1]);
            *(float2*)(C + (size_t)(row + 8) * N + col) =
                make_float2(acc[mi][nf][2], acc[mi][nf][3]);
        }
    }
}

// =====================================================================
// Depthwise causal conv (width 4) + bias + SiLU, float4-vectorized
// =====================================================================
__global__ void conv_silu_kernel(const float* __restrict__ xz,
                                 const float* __restrict__ cw,
                                 const float* __restrict__ cb,
                                 float* __restrict__ xconv)
{
    int idx = blockIdx.x * blockDim.x + threadIdx.x;   // 0 .. B*T*D/4-1
    if (idx >= MROWS * DD / 4) return;
    int d4 = idx & (DD / 4 - 1);     // 0..255
    int bt = idx >> 8;
    int t  = bt & (TT - 1);
    int b  = bt >> 11;

    // per-channel taps (4 channels x 4 taps)
    float4 cw0 = ((const float4*)cw)[d4 * 4 + 0];
    float4 cw1 = ((const float4*)cw)[d4 * 4 + 1];
    float4 cw2 = ((const float4*)cw)[d4 * 4 + 2];
    float4 cw3 = ((const float4*)cw)[d4 * 4 + 3];
    float4 acc = ((const float4*)cb)[d4];

    #pragma unroll
    for (int j = 0; j < DCONV; j++) {
        int tt = t - (DCONV - 1) + j;
        if (tt >= 0) {
            float4 xv = *(const float4*)(xz + (size_t)(b * TT + tt) * E2 + d4 * 4);
            float w0 = (&cw0.x)[j], w1 = (&cw1.x)[j], w2 = (&cw2.x)[j], w3 = (&cw3.x)[j];
            acc.x = fmaf(xv.x, w0, acc.x);
            acc.y = fmaf(xv.y, w1, acc.y);
            acc.z = fmaf(xv.z, w2, acc.z);
            acc.w = fmaf(xv.w, w3, acc.w);
        }
    }
    acc.x = acc.x / (1.0f + __expf(-acc.x));
    acc.y = acc.y / (1.0f + __expf(-acc.y));
    acc.z = acc.z / (1.0f + __expf(-acc.z));
    acc.w = acc.w / (1.0f + __expf(-acc.w));
    *(float4*)(xconv + (size_t)bt * DD + d4 * 4) = acc;
}

// =====================================================================
// Tiled x_proj: block = (33,8) threads, 32 rows per block.
// =====================================================================
__global__ void xproj_tiled(const float* __restrict__ xconv,
                            const float* __restrict__ W,
                            float* __restrict__ params)
{
    __shared__ float sx[32][68];
    const int e  = threadIdx.x;   // 0..32
    const int rg = threadIdx.y;   // 0..7
    const int flat = rg * 33 + e;
    const int row0 = blockIdx.x * 32;

    float acc[4] = {0.f, 0.f, 0.f, 0.f};

    for (int k0 = 0; k0 < DD; k0 += 64) {
        __syncthreads();
        for (int c = flat; c < 512; c += 264) {
            int ri = c >> 4;
            int k4 = c & 15;
            float4 v = *(const float4*)(xconv + (size_t)(row0 + ri) * DD + k0 + k4 * 4);
            *(float4*)&sx[ri][k4 * 4] = v;
        }
        __syncthreads();
        const float* wrow = W + (size_t)e * DD + k0;
        #pragma unroll
        for (int k4 = 0; k4 < 16; k4++) {
            float4 w4 = *(const float4*)(wrow + k4 * 4);
            #pragma unroll
            for (int j = 0; j < 4; j++) {
                const float* sxr = sx[rg * 4 + j];
                acc[j] = fmaf(sxr[k4*4+0], w4.x, acc[j]);
                acc[j] = fmaf(sxr[k4*4+1], w4.y, acc[j]);
                acc[j] = fmaf(sxr[k4*4+2], w4.z, acc[j]);
                acc[j] = fmaf(sxr[k4*4+3], w4.w, acc[j]);
            }
        }
    }
    #pragma unroll
    for (int j = 0; j < 4; j++)
        params[(size_t)(row0 + rg * 4 + j) * NPAR + e] = acc[j];
}

// =====================================================================
// Chunked scan, pass A (fast exp-chain path when A_log = log(1..N)).
// =====================================================================
__global__ __launch_bounds__(128) void scanA_kernel(const float* __restrict__ params,
                                                    const float* __restrict__ xconv,
                                                    const float* __restrict__ dtw,
                                                    const float* __restrict__ dtb,
                                                    const float* __restrict__ A_log,
                                                    float* __restrict__ Pout,
                                                    float* __restrict__ hend)
{
    const int dg = blockIdx.x & 7;
    const int c  = (blockIdx.x >> 3) & (NCH - 1);
    const int b  = blockIdx.x >> 8;
    const int d  = dg * 128 + threadIdx.x;

    float a[NN];
    #pragma unroll
    for (int n = 0; n < NN; n++)
        a[n] = -expf(A_log[(size_t)d * NN + n]);
    const float w    = dtw[d];
    const float bias = dtb[d];

    bool fast = true;
    #pragma unroll
    for (int n = 1; n < NN; n++)
        fast = fast && (fabsf(a[n] - (float)(n + 1) * a[0]) <= 1e-4f * fabsf(a[n]) + 1e-12f);

    float h[NN], P[NN];
    #pragma unroll
    for (int n = 0; n < NN; n++) { h[n] = 0.f; P[n] = 1.f; }

    const size_t rowbase = (size_t)b * TT + (size_t)c * CHL;
    if (fast) {
        const float a0 = a[0];
        for (int t = 0; t < CHL; t++) {
            const size_t r = rowbase + t;
            const float* p = params + r * NPAR;
            float v  = fmaf(p[32], w, bias);
            float dt = (v > 20.f) ? v : __logf(1.0f + __expf(v));
            float dtx = dt * xconv[r * DD + d];
            float q = __expf(dt * a0);
            float e = q;
            #pragma unroll
            for (int n = 0; n < NN; n++) {
                h[n] = fmaf(e, h[n], dtx * p[n]);
                P[n] *= e;
                e *= q;
            }
        }
    } else {
        for (int t = 0; t < CHL; t++) {
            const size_t r = rowbase + t;
            const float* p = params + r * NPAR;
            float v  = fmaf(p[32], w, bias);
            float dt = (v > 20.f) ? v : __logf(1.0f + __expf(v));
            float dtx = dt * xconv[r * DD + d];
            #pragma unroll
            for (int n = 0; n < NN; n++) {
                float e = __expf(dt * a[n]);
                h[n] = fmaf(e, h[n], dtx * p[n]);
                P[n] *= e;
            }
        }
    }
    const size_t o = ((size_t)(b * NCH + c) * NN) * DD + d;
    #pragma unroll
    for (int n = 0; n < NN; n++) {
        hend[o + (size_t)n * DD] = h[n];
        Pout[o + (size_t)n * DD] = P[n];
    }
}

// =====================================================================
// Pass B: sequential chunk combine.
// =====================================================================
__global__ void scanB_kernel(const float* __restrict__ P,
                             const float* __restrict__ hend,
                             float* __restrict__ hini)
{
    int gid = blockIdx.x * blockDim.x + threadIdx.x;
    if (gid >= BB * DD) return;
    int d = gid & (DD - 1);
    int b = gid >> 10;

    float h[NN];
    #pragma unroll
    for (int n = 0; n < NN; n++) h[n] = 0.f;

    for (int c = 0; c < NCH; c++) {
        const size_t o = ((size_t)(b * NCH + c) * NN) * DD + d;
        #pragma unroll
        for (int n = 0; n < NN; n++) {
            hini[o + (size_t)n * DD] = h[n];
            h[n] = fmaf(P[o + (size_t)n * DD], h[n], hend[o + (size_t)n * DD]);
        }
    }
}

// =====================================================================
// Pass C: re-run chunks from h_init; emit y=(h·C)*silu(z) as fp16.
// =====================================================================
__global__ __launch_bounds__(128) void scanC_kernel(const float* __restrict__ params,
                                                    const float* __restrict__ xconv,
                                                    const float* __restrict__ xz,
                                                    const float* __restrict__ dtw,
                                                    const float* __restrict__ dtb,
                                                    const float* __restrict__ A_log,
                                                    const float* __restrict__ hini,
                                                    __half* __restrict__ yh)
{
    const int dg = blockIdx.x & 7;
    const int c  = (blockIdx.x >> 3) & (NCH - 1);
    const int b  = blockIdx.x >> 8;
    const int d  = dg * 128 + threadIdx.x;

    float a[NN];
    #pragma unroll
    for (int n = 0; n < NN; n++)
        a[n] = -expf(A_log[(size_t)d * NN + n]);
    const float w    = dtw[d];
    const float bias = dtb[d];

    bool fast = true;
    #pragma unroll
    for (int n = 1; n < NN; n++)
        fast = fast && (fabsf(a[n] - (float)(n + 1) * a[0]) <= 1e-4f * fabsf(a[n]) + 1e-12f);

    float h[NN];
    const size_t o = ((size_t)(b * NCH + c) * NN) * DD + d;
    #pragma unroll
    for (int n = 0; n < NN; n++) h[n] = hini[o + (size_t)n * DD];

    const size_t rowbase = (size_t)b * TT + (size_t)c * CHL;
    if (fast) {
        const float a0 = a[0];
        for (int t = 0; t < CHL; t++) {
            const size_t r = rowbase + t;
            const float* p = params + r * NPAR;
            float v  = fmaf(p[32], w, bias);
            float dt = (v > 20.f) ? v : __logf(1.0f + __expf(v));
            float dtx = dt * xconv[r * DD + d];
            float zv  = xz[r * E2 + DD + d];
            float q = __expf(dt * a0);
            float e = q;
            float yv = 0.f;
            #pragma unroll
            for (int n = 0; n < NN; n++) {
                h[n] = fmaf(e, h[n], dtx * p[n]);
                yv = fmaf(h[n], p[NN + n], yv);
                e *= q;
            }
            float sil = zv / (1.0f + __expf(-zv));
            yh[r * DD + d] = __float2half_rn(yv * sil);
        }
    } else {
        for (int t = 0; t < CHL; t++) {
            const size_t r = rowbase + t;
            const float* p = params + r * NPAR;
            float v  = fmaf(p[32], w, bias);
            float dt = (v > 20.f) ? v : __logf(1.0f + __expf(v));
            float dtx = dt * xconv[r * DD + d];
            float zv  = xz[r * E2 + DD + d];
            float yv = 0.f;
            #pragma unroll
            for (int n = 0; n < NN; n++) {
                float e = __expf(dt * a[n]);
                h[n] = fmaf(e, h[n], dtx * p[n]);
                yv = fmaf(h[n], p[NN + n], yv);
            }
            float sil = zv / (1.0f + __expf(-zv));
            yh[r * DD + d] = __float2half_rn(yv * sil);
        }
    }
}

// =====================================================================
// launch
// =====================================================================
extern "C" void kernel_launch(void* const* d_in, const int* in_sizes, int n_in,
                              void* d_out, int out_size)
{
    const float* x         = (const float*)d_in[0];
    const float* in_proj_w = (const float*)d_in[1];
    const float* conv_w    = (const float*)d_in[2];
    const float* conv_b    = (const float*)d_in[3];
    const float* x_proj_w  = (const float*)d_in[4];
    const float* dt_proj_w = (const float*)d_in[5];
    const float* dt_proj_b = (const float*)d_in[6];
    const float* A_log     = (const float*)d_in[7];
    const float* out_proj_w= (const float*)d_in[8];
    float* out = (float*)d_out;

    float *xz, *xconv, *params, *P, *hend, *hini;
    __half *xh, *w1hi, *w1lo, *w2hi, *w2lo, *yh;
    cudaGetSymbolAddress((void**)&xz,     g_xz);
    cudaGetSymbolAddress((void**)&xconv,  g_xconv);
    cudaGetSymbolAddress((void**)&params, g_params);
    cudaGetSymbolAddress((void**)&P,      g_P);
    cudaGetSymbolAddress((void**)&hend,   g_hend);
    cudaGetSymbolAddress((void**)&hini,   g_hini);
    cudaGetSymbolAddress((void**)&xh,     g_xh);
    cudaGetSymbolAddress((void**)&w1hi,   g_w1hi);
    cudaGetSymbolAddress((void**)&w1lo,   g_w1lo);
    cudaGetSymbolAddress((void**)&w2hi,   g_w2hi);
    cudaGetSymbolAddress((void**)&w2lo,   g_w2lo);
    cudaGetSymbolAddress((void**)&yh,     g_yh);

    cudaFuncSetAttribute(gemm_fp16_2t,
                         cudaFuncAttributeMaxDynamicSharedMemorySize, GEMM_SMEM);

    // 0) convert/split
    tohalf_kernel<<<(MROWS*DD/4 + 255)/256, 256>>>(x, xh, MROWS*DD/4);
    splitw_kernel<<<(E2*DD/4    + 255)/256, 256>>>(in_proj_w, w1hi, w1lo, E2*DD/4);
    splitw_kernel<<<(DD*DD/4    + 255)/256, 256>>>(out_proj_w, w2hi, w2lo, DD*DD/4);

    // 1) in_proj: (4096,1024) @ (2048,1024)^T -> (4096,2048)
    {
        dim3 grid(E2 / 128, MROWS / 128);
        gemm_fp16_2t<<<grid, 256, GEMM_SMEM>>>(xh, w1hi, w1lo, xz, MROWS, E2, DD);
    }
    // 2) depthwise conv + SiLU
    conv_silu_kernel<<<(MROWS*DD/4 + 255)/256, 256>>>(xz, conv_w, conv_b, xconv);
    // 3) x_proj (tiled)
    {
        dim3 blk(33, 8);
        xproj_tiled<<<MROWS / 32, blk>>>(xconv, x_proj_w, params);
    }
    // 4) chunked selective scan
    scanA_kernel<<<BB * NCH * (DD/128), 128>>>(params, xconv, dt_proj_w, dt_proj_b, A_log, P, hend);
    scanB_kernel<<<(BB*DD + 255)/256, 256>>>(P, hend, hini);
    scanC_kernel<<<BB * NCH * (DD/128), 128>>>(params, xconv, xz, dt_proj_w, dt_proj_b, A_log, hini, yh);
    // 5) out_proj: (4096,1024) @ (1024,1024)^T -> (4096,1024)
    {
        dim3 grid(DD / 128, MROWS / 128);
        gemm_fp16_2t<<<grid, 256, GEMM_SMEM>>>(yh, w2hi, w2lo, out, MROWS, DD, DD);
    }
}

// round 8
// speedup vs baseline: 1.4094x; 1.0442x over previous
#include <cuda_runtime.h>
#include <cuda_fp16.h>
#include <cstdint>

// Problem dims (fixed by the reference)
#define BB 2
#define TT 2048
#define DD 1024
#define NN 16
#define DCONV 4
#define MROWS (BB*TT)          // 4096
#define E2 (2*DD)              // 2048
#define NPAR (2*NN+1)          // 33
#define NCH 32                 // scan chunks
#define CHL (TT/NCH)           // 64 steps per chunk

// ---------- scratch (static device allocations only) ----------
__device__ float g_xz[(size_t)MROWS * E2];        // in_proj output (x_in | z)
__device__ float g_xconv[(size_t)MROWS * DD];     // conv+silu output
__device__ float g_params[(size_t)MROWS * NPAR];  // x_proj output (B,C,dt_raw)
__device__ __half g_xh [(size_t)MROWS * DD];      // x in fp16
__device__ __half g_w1hi[(size_t)E2 * DD], g_w1lo[(size_t)E2 * DD];
__device__ __half g_w2hi[(size_t)DD * DD], g_w2lo[(size_t)DD * DD];
__device__ __half g_yh [(size_t)MROWS * DD];      // scan output in fp16
__device__ float g_P   [(size_t)BB * NCH * NN * DD];
__device__ float g_hend[(size_t)BB * NCH * NN * DD];
__device__ float g_hini[(size_t)BB * NCH * NN * DD];

// =====================================================================
// Merged precision prep:
//  range0: x -> fp16            range1: w1 -> fp16 hi/lo
//  range2: w2 -> fp16 hi/lo     (all in float4 units)
// =====================================================================
#define N_X4  (MROWS*DD/4)     // 1048576
#define N_W14 (E2*DD/4)        //  524288
#define N_W24 (DD*DD/4)        //  262144
#define N_PREP (N_X4 + N_W14 + N_W24)

__device__ __forceinline__ void split_one(float4 v, __half* hi, __half* lo, int i) {
    __half hx = __float2half_rn(v.x);
    __half hy = __float2half_rn(v.y);
    __half hz = __float2half_rn(v.z);
    __half hw = __float2half_rn(v.w);
    __half2 h01; h01.x = hx; h01.y = hy;
    __half2 h23; h23.x = hz; h23.y = hw;
    ((__half2*)hi)[i*2]   = h01;
    ((__half2*)hi)[i*2+1] = h23;
    __half2 l01, l23;
    l01.x = __float2half_rn(v.x - __half2float(hx));
    l01.y = __float2half_rn(v.y - __half2float(hy));
    l23.x = __float2half_rn(v.z - __half2float(hz));
    l23.y = __float2half_rn(v.w - __half2float(hw));
    ((__half2*)lo)[i*2]   = l01;
    ((__half2*)lo)[i*2+1] = l23;
}

__global__ void prep_kernel(const float* __restrict__ x,
                            const float* __restrict__ w1,
                            const float* __restrict__ w2,
                            __half* __restrict__ xh,
                            __half* __restrict__ w1hi, __half* __restrict__ w1lo,
                            __half* __restrict__ w2hi, __half* __restrict__ w2lo)
{
    int i = blockIdx.x * blockDim.x + threadIdx.x;
    if (i < N_X4) {
        float4 v = ((const float4*)x)[i];
        ((__half2*)xh)[i*2]   = __floats2half2_rn(v.x, v.y);
        ((__half2*)xh)[i*2+1] = __floats2half2_rn(v.z, v.w);
    } else if (i < N_X4 + N_W14) {
        int j = i - N_X4;
        split_one(((const float4*)w1)[j], w1hi, w1lo, j);
    } else if (i < N_PREP) {
        int j = i - N_X4 - N_W14;
        split_one(((const float4*)w2)[j], w2hi, w2lo, j);
    }
}

// =====================================================================
// Tensor-core GEMM, fp16 2-term: C[M,N] = A16[M,K] @ (Whi+Wlo)[N,K]^T
// Block 128x128, BK=32, 256 threads (8 warps), warp tile 64x32,
// 3-stage cp.async pipeline, single __syncthreads per k-iter,
// __launch_bounds__(256,2) -> 2 blocks/SM.     (unchanged from R7)
// =====================================================================
#define GLDA 40                       // half elems per smem row (32 + 8 pad)
#define ARR_B  (128*GLDA*2)           // bytes per operand array = 10240
#define STAGE_B (3*ARR_B)             // A, Whi, Wlo = 30720
#define NSTAGE 3
#define GEMM_SMEM (NSTAGE*STAGE_B)    // 92160 bytes

__device__ __forceinline__ void mma16816h(float* c, const uint32_t* a, const uint32_t* b) {
    asm volatile(
        "mma.sync.aligned.m16n8k16.row.col.f32.f16.f16.f32 "
        "{%0,%1,%2,%3}, {%4,%5,%6,%7}, {%8,%9}, {%0,%1,%2,%3};"
        : "+f"(c[0]), "+f"(c[1]), "+f"(c[2]), "+f"(c[3])
        : "r"(a[0]), "r"(a[1]), "r"(a[2]), "r"(a[3]), "r"(b[0]), "r"(b[1]));
}
__device__ __forceinline__ void ldm4(uint32_t* r, uint32_t addr) {
    asm volatile(
        "ldmatrix.sync.aligned.m8n8.x4.shared.b16 {%0,%1,%2,%3}, [%4];"
        : "=r"(r[0]), "=r"(r[1]), "=r"(r[2]), "=r"(r[3]) : "r"(addr));
}
__device__ __forceinline__ void cpasync16(uint32_t dst, const void* src) {
    asm volatile("cp.async.cg.shared.global [%0], [%1], 16;" :: "r"(dst), "l"(src));
}

__global__ __launch_bounds__(256, 2) void gemm_fp16_2t(
    const __half* __restrict__ A,
    const __half* __restrict__ Whi, const __half* __restrict__ Wlo,
    float* __restrict__ C, int M, int N, int K)
{
    extern __shared__ __align__(16) char dsm[];

    const int tid  = threadIdx.x;
    const int lane = tid & 31;
    const int warp = tid >> 5;
    const int wm   = warp >> 2;          // 0..1
    const int wn   = warp & 3;           // 0..3
    const int brow = blockIdx.y * 128;
    const int bcol = blockIdx.x * 128;

    float acc[4][4][4];
    #pragma unroll
    for (int i = 0; i < 4; i++)
        #pragma unroll
        for (int j = 0; j < 4; j++)
            #pragma unroll
            for (int k = 0; k < 4; k++) acc[i][j][k] = 0.f;

    const uint32_t sbase = (uint32_t)__cvta_generic_to_shared(dsm);

    const __half* srcs[3];
    srcs[0] = A   + (size_t)(brow) * K;
    srcs[1] = Whi + (size_t)(bcol) * K;
    srcs[2] = Wlo + (size_t)(bcol) * K;

    uint32_t offA[4];
    #pragma unroll
    for (int mi = 0; mi < 4; mi++) {
        int row = wm * 64 + mi * 16 + (lane & 15);
        int ko  = (lane >> 4) * 8;
        offA[mi] = (uint32_t)(row * GLDA + ko) * 2u;
    }
    uint32_t offB[2];
    #pragma unroll
    for (int ni2 = 0; ni2 < 2; ni2++) {
        int row = wn * 32 + ni2 * 16 + (lane & 7) + ((lane >> 4) << 3);
        int ko  = ((lane >> 3) & 1) * 8;
        offB[ni2] = (uint32_t)(row * GLDA + ko) * 2u;
    }

    const int NK = K / 32;

    auto load_slab = [&](int slab, int stage) {
        const uint32_t stB = sbase + (uint32_t)stage * STAGE_B;
        #pragma unroll
        for (int arr = 0; arr < 3; arr++) {
            const __half* sp = srcs[arr] + slab * 32;
            #pragma unroll
            for (int j = 0; j < 2; j++) {
                int idx = tid + j * 256;       // 0..511
                int row = idx >> 2;
                int kc  = idx & 3;
                uint32_t dst = stB + (uint32_t)arr * ARR_B + (uint32_t)(row * GLDA + kc * 8) * 2u;
                cpasync16(dst, sp + (size_t)row * K + kc * 8);
            }
        }
        asm volatile("cp.async.commit_group;");
    };

    load_slab(0, 0);
    load_slab(1, 1);

    for (int kt = 0; kt < NK; kt++) {
        const int stage = kt % 3;
        if (kt < NK - 1) asm volatile("cp.async.wait_group 1;");
        else             asm volatile("cp.async.wait_group 0;");
        __syncthreads();

        if (kt + 2 < NK) load_slab(kt + 2, (kt + 2) % 3);

        const uint32_t stA   = sbase + (uint32_t)stage * STAGE_B;
        const uint32_t stWhi = stA + ARR_B;
        const uint32_t stWlo = stA + 2 * ARR_B;

        #pragma unroll
        for (int ks = 0; ks < 2; ks++) {
            const uint32_t kadd = (uint32_t)(ks * 32);
            uint32_t a[4][4], bhi[2][4], blo[2][4];
            #pragma unroll
            for (int ni2 = 0; ni2 < 2; ni2++) {
                ldm4(bhi[ni2], stWhi + offB[ni2] + kadd);
                ldm4(blo[ni2], stWlo + offB[ni2] + kadd);
            }
            #pragma unroll
            for (int mi = 0; mi < 4; mi++)
                ldm4(a[mi], stA + offA[mi] + kadd);
            #pragma unroll
            for (int mi = 0; mi < 4; mi++) {
                #pragma unroll
                for (int nf = 0; nf < 4; nf++) {
                    const int ni2 = nf >> 1;
                    const int s   = (nf & 1) * 2;
                    uint32_t bh[2] = { bhi[ni2][s], bhi[ni2][s + 1] };
                    uint32_t bl[2] = { blo[ni2][s], blo[ni2][s + 1] };
                    mma16816h(acc[mi][nf], a[mi], bh);
                    mma16816h(acc[mi][nf], a[mi], bl);
                }
            }
        }
    }

    const int gid = lane >> 2;
    const int tig = lane & 3;
    #pragma unroll
    for (int mi = 0; mi < 4; mi++) {
        #pragma unroll
        for (int nf = 0; nf < 4; nf++) {
            int row = brow + wm * 64 + mi * 16 + gid;
            int col = bcol + wn * 32 + nf * 8 + tig * 2;
            *(float2*)(C + (size_t)row * N + col) =
                make_float2(acc[mi][nf][0], acc[mi][nf][1]);
            *(float2*)(C + (size_t)(row + 8) * N + col) =
                make_float2(acc[mi][nf][2], acc[mi][nf][3]);
        }
    }
}

// =====================================================================
// Depthwise causal conv (width 4) + bias + SiLU, float4-vectorized
// =====================================================================
__global__ void conv_silu_kernel(const float* __restrict__ xz,
                                 const float* __restrict__ cw,
                                 const float* __restrict__ cb,
                                 float* __restrict__ xconv)
{
    int idx = blockIdx.x * blockDim.x + threadIdx.x;
    if (idx >= MROWS * DD / 4) return;
    int d4 = idx & (DD / 4 - 1);
    int bt = idx >> 8;
    int t  = bt & (TT - 1);
    int b  = bt >> 11;

    float4 cw0 = ((const float4*)cw)[d4 * 4 + 0];
    float4 cw1 = ((const float4*)cw)[d4 * 4 + 1];
    float4 cw2 = ((const float4*)cw)[d4 * 4 + 2];
    float4 cw3 = ((const float4*)cw)[d4 * 4 + 3];
    float4 acc = ((const float4*)cb)[d4];

    #pragma unroll
    for (int j = 0; j < DCONV; j++) {
        int tt = t - (DCONV - 1) + j;
        if (tt >= 0) {
            float4 xv = *(const float4*)(xz + (size_t)(b * TT + tt) * E2 + d4 * 4);
            float w0 = (&cw0.x)[j], w1 = (&cw1.x)[j], w2 = (&cw2.x)[j], w3 = (&cw3.x)[j];
            acc.x = fmaf(xv.x, w0, acc.x);
            acc.y = fmaf(xv.y, w1, acc.y);
            acc.z = fmaf(xv.z, w2, acc.z);
            acc.w = fmaf(xv.w, w3, acc.w);
        }
    }
    acc.x = acc.x / (1.0f + __expf(-acc.x));
    acc.y = acc.y / (1.0f + __expf(-acc.y));
    acc.z = acc.z / (1.0f + __expf(-acc.z));
    acc.w = acc.w / (1.0f + __expf(-acc.w));
    *(float4*)(xconv + (size_t)bt * DD + d4 * 4) = acc;
}

// =====================================================================
// Tiled x_proj: block = (33,8) threads, 32 rows per block.
// =====================================================================
__global__ void xproj_tiled(const float* __restrict__ xconv,
                            const float* __restrict__ W,
                            float* __restrict__ params)
{
    __shared__ float sx[32][68];
    const int e  = threadIdx.x;   // 0..32
    const int rg = threadIdx.y;   // 0..7
    const int flat = rg * 33 + e;
    const int row0 = blockIdx.x * 32;

    float acc[4] = {0.f, 0.f, 0.f, 0.f};

    for (int k0 = 0; k0 < DD; k0 += 64) {
        __syncthreads();
        for (int c = flat; c < 512; c += 264) {
            int ri = c >> 4;
            int k4 = c & 15;
            float4 v = *(const float4*)(xconv + (size_t)(row0 + ri) * DD + k0 + k4 * 4);
            *(float4*)&sx[ri][k4 * 4] = v;
        }
        __syncthreads();
        const float* wrow = W + (size_t)e * DD + k0;
        #pragma unroll
        for (int k4 = 0; k4 < 16; k4++) {
            float4 w4 = *(const float4*)(wrow + k4 * 4);
            #pragma unroll
            for (int j = 0; j < 4; j++) {
                const float* sxr = sx[rg * 4 + j];
                acc[j] = fmaf(sxr[k4*4+0], w4.x, acc[j]);
                acc[j] = fmaf(sxr[k4*4+1], w4.y, acc[j]);
                acc[j] = fmaf(sxr[k4*4+2], w4.z, acc[j]);
                acc[j] = fmaf(sxr[k4*4+3], w4.w, acc[j]);
            }
        }
    }
    #pragma unroll
    for (int j = 0; j < 4; j++)
        params[(size_t)(row0 + rg * 4 + j) * NPAR + e] = acc[j];
}

// =====================================================================
// Scan pass A. 128-thread blocks; chunk params staged in padded smem
// (36-float rows -> 8x LDS.128 + 1 LDS.32 broadcast per step instead
// of 33 scalar LDG). Fast exp-chain path when A_log = log(1..N).
// =====================================================================
#define SPQ (CHL*NPAR/4)   // 528 float4 per chunk

__global__ __launch_bounds__(128) void scanA_kernel(const float* __restrict__ params,
                                                    const float* __restrict__ xconv,
                                                    const float* __restrict__ dtw,
                                                    const float* __restrict__ dtb,
                                                    const float* __restrict__ A_log,
                                                    float* __restrict__ Pout,
                                                    float* __restrict__ hend)
{
    __shared__ float sp[CHL][36];
    const int dg = blockIdx.x & 7;
    const int c  = (blockIdx.x >> 3) & (NCH - 1);
    const int b  = blockIdx.x >> 8;
    const int d  = dg * 128 + threadIdx.x;
    const size_t rowbase = (size_t)b * TT + (size_t)c * CHL;

    // stage params chunk (contiguous, 16B aligned)
    {
        const float4* src = (const float4*)(params + rowbase * NPAR);
        for (int i = threadIdx.x; i < SPQ; i += 128) {
            float4 v = src[i];
            int e = i * 4;
            #pragma unroll
            for (int j = 0; j < 4; j++) {
                int ee = e + j;
                sp[ee / NPAR][ee % NPAR] = (&v.x)[j];
            }
        }
    }

    float a[NN];
    #pragma unroll
    for (int n = 0; n < NN; n++)
        a[n] = -expf(A_log[(size_t)d * NN + n]);
    const float w    = dtw[d];
    const float bias = dtb[d];

    bool fast = true;
    #pragma unroll
    for (int n = 1; n < NN; n++)
        fast = fast && (fabsf(a[n] - (float)(n + 1) * a[0]) <= 1e-4f * fabsf(a[n]) + 1e-12f);

    float h[NN], P[NN];
    #pragma unroll
    for (int n = 0; n < NN; n++) { h[n] = 0.f; P[n] = 1.f; }

    __syncthreads();

    if (fast) {
        const float a0 = a[0];
        for (int t = 0; t < CHL; t++) {
            float pv[16], cv[16];
            *(float4*)&pv[0]  = *(const float4*)&sp[t][0];
            *(float4*)&pv[4]  = *(const float4*)&sp[t][4];
            *(float4*)&pv[8]  = *(const float4*)&sp[t][8];
            *(float4*)&pv[12] = *(const float4*)&sp[t][12];
            *(float4*)&cv[0]  = *(const float4*)&sp[t][16];
            *(float4*)&cv[4]  = *(const float4*)&sp[t][20];
            *(float4*)&cv[8]  = *(const float4*)&sp[t][24];
            *(float4*)&cv[12] = *(const float4*)&sp[t][28];
            float v  = fmaf(sp[t][32], w, bias);
            float dt = (v > 20.f) ? v : __logf(1.0f + __expf(v));
            float dtx = dt * xconv[(rowbase + t) * DD + d];
            float q = __expf(dt * a0);
            float e = q;
            #pragma unroll
            for (int n = 0; n < NN; n++) {
                h[n] = fmaf(e, h[n], dtx * pv[n]);
                P[n] *= e;
                e *= q;
            }
            (void)cv;   // C unused in pass A
        }
    } else {
        for (int t = 0; t < CHL; t++) {
            float pv[16];
            *(float4*)&pv[0]  = *(const float4*)&sp[t][0];
            *(float4*)&pv[4]  = *(const float4*)&sp[t][4];
            *(float4*)&pv[8]  = *(const float4*)&sp[t][8];
            *(float4*)&pv[12] = *(const float4*)&sp[t][12];
            float v  = fmaf(sp[t][32], w, bias);
            float dt = (v > 20.f) ? v : __logf(1.0f + __expf(v));
            float dtx = dt * xconv[(rowbase + t) * DD + d];
            #pragma unroll
            for (int n = 0; n < NN; n++) {
                float e = __expf(dt * a[n]);
                h[n] = fmaf(e, h[n], dtx * pv[n]);
                P[n] *= e;
            }
        }
    }
    const size_t o = ((size_t)(b * NCH + c) * NN) * DD + d;
    #pragma unroll
    for (int n = 0; n < NN; n++) {
        hend[o + (size_t)n * DD] = h[n];
        Pout[o + (size_t)n * DD] = P[n];
    }
}

// =====================================================================
// Pass B: sequential chunk combine.
// =====================================================================
__global__ void scanB_kernel(const float* __restrict__ P,
                             const float* __restrict__ hend,
                             float* __restrict__ hini)
{
    int gid = blockIdx.x * blockDim.x + threadIdx.x;
    if (gid >= BB * DD) return;
    int d = gid & (DD - 1);
    int b = gid >> 10;

    float h[NN];
    #pragma unroll
    for (int n = 0; n < NN; n++) h[n] = 0.f;

    for (int c = 0; c < NCH; c++) {
        const size_t o = ((size_t)(b * NCH + c) * NN) * DD + d;
        #pragma unroll
        for (int n = 0; n < NN; n++) {
            hini[o + (size_t)n * DD] = h[n];
            h[n] = fmaf(P[o + (size_t)n * DD], h[n], hend[o + (size_t)n * DD]);
        }
    }
}

// =====================================================================
// Pass C: re-run chunks from h_init; emit y=(h·C)*silu(z) as fp16.
// Same smem staging as pass A.
// =====================================================================
__global__ __launch_bounds__(128) void scanC_kernel(const float* __restrict__ params,
                                                    const float* __restrict__ xconv,
                                                    const float* __restrict__ xz,
                                                    const float* __restrict__ dtw,
                                                    const float* __restrict__ dtb,
                                                    const float* __restrict__ A_log,
                                                    const float* __restrict__ hini,
                                                    __half* __restrict__ yh)
{
    __shared__ float sp[CHL][36];
    const int dg = blockIdx.x & 7;
    const int c  = (blockIdx.x >> 3) & (NCH - 1);
    const int b  = blockIdx.x >> 8;
    const int d  = dg * 128 + threadIdx.x;
    const size_t rowbase = (size_t)b * TT + (size_t)c * CHL;

    {
        const float4* src = (const float4*)(params + rowbase * NPAR);
        for (int i = threadIdx.x; i < SPQ; i += 128) {
            float4 v = src[i];
            int e = i * 4;
            #pragma unroll
            for (int j = 0; j < 4; j++) {
                int ee = e + j;
                sp[ee / NPAR][ee % NPAR] = (&v.x)[j];
            }
        }
    }

    float a[NN];
    #pragma unroll
    for (int n = 0; n < NN; n++)
        a[n] = -expf(A_log[(size_t)d * NN + n]);
    const float w    = dtw[d];
    const float bias = dtb[d];

    bool fast = true;
    #pragma unroll
    for (int n = 1; n < NN; n++)
        fast = fast && (fabsf(a[n] - (float)(n + 1) * a[0]) <= 1e-4f * fabsf(a[n]) + 1e-12f);

    float h[NN];
    const size_t o = ((size_t)(b * NCH + c) * NN) * DD + d;
    #pragma unroll
    for (int n = 0; n < NN; n++) h[n] = hini[o + (size_t)n * DD];

    __syncthreads();

    if (fast) {
        const float a0 = a[0];
        for (int t = 0; t < CHL; t++) {
            const size_t r = rowbase + t;
            float pv[16], cv[16];
            *(float4*)&pv[0]  = *(const float4*)&sp[t][0];
            *(float4*)&pv[4]  = *(const float4*)&sp[t][4];
            *(float4*)&pv[8]  = *(const float4*)&sp[t][8];
            *(float4*)&pv[12] = *(const float4*)&sp[t][12];
            *(float4*)&cv[0]  = *(const float4*)&sp[t][16];
            *(float4*)&cv[4]  = *(const float4*)&sp[t][20];
            *(float4*)&cv[8]  = *(const float4*)&sp[t][24];
            *(float4*)&cv[12] = *(const float4*)&sp[t][28];
            float v  = fmaf(sp[t][32], w, bias);
            float dt = (v > 20.f) ? v : __logf(1.0f + __expf(v));
            float dtx = dt * xconv[r * DD + d];
            float zv  = xz[r * E2 + DD + d];
            float q = __expf(dt * a0);
            float e = q;
            float yv = 0.f;
            #pragma unroll
            for (int n = 0; n < NN; n++) {
                h[n] = fmaf(e, h[n], dtx * pv[n]);
                yv = fmaf(h[n], cv[n], yv);
                e *= q;
            }
            float sil = zv / (1.0f + __expf(-zv));
            yh[r * DD + d] = __float2half_rn(yv * sil);
        }
    } else {
        for (int t = 0; t < CHL; t++) {
            const size_t r = rowbase + t;
            float pv[16], cv[16];
            *(float4*)&pv[0]  = *(const float4*)&sp[t][0];
            *(float4*)&pv[4]  = *(const float4*)&sp[t][4];
            *(float4*)&pv[8]  = *(const float4*)&sp[t][8];
            *(float4*)&pv[12] = *(const float4*)&sp[t][12];
            *(float4*)&cv[0]  = *(const float4*)&sp[t][16];
            *(float4*)&cv[4]  = *(const float4*)&sp[t][20];
            *(float4*)&cv[8]  = *(const float4*)&sp[t][24];
            *(float4*)&cv[12] = *(const float4*)&sp[t][28];
            float v  = fmaf(sp[t][32], w, bias);
            float dt = (v > 20.f) ? v : __logf(1.0f + __expf(v));
            float dtx = dt * xconv[r * DD + d];
            float zv  = xz[r * E2 + DD + d];
            float yv = 0.f;
            #pragma unroll
            for (int n = 0; n < NN; n++) {
                float e = __expf(dt * a[n]);
                h[n] = fmaf(e, h[n], dtx * pv[n]);
                yv = fmaf(h[n], cv[n], yv);
            }
            float sil = zv / (1.0f + __expf(-zv));
            yh[r * DD + d] = __float2half_rn(yv * sil);
        }
    }
}

// =====================================================================
// launch
// =====================================================================
extern "C" void kernel_launch(void* const* d_in, const int* in_sizes, int n_in,
                              void* d_out, int out_size)
{
    const float* x         = (const float*)d_in[0];
    const float* in_proj_w = (const float*)d_in[1];
    const float* conv_w    = (const float*)d_in[2];
    const float* conv_b    = (const float*)d_in[3];
    const float* x_proj_w  = (const float*)d_in[4];
    const float* dt_proj_w = (const float*)d_in[5];
    const float* dt_proj_b = (const float*)d_in[6];
    const float* A_log     = (const float*)d_in[7];
    const float* out_proj_w= (const float*)d_in[8];
    float* out = (float*)d_out;

    float *xz, *xconv, *params, *P, *hend, *hini;
    __half *xh, *w1hi, *w1lo, *w2hi, *w2lo, *yh;
    cudaGetSymbolAddress((void**)&xz,     g_xz);
    cudaGetSymbolAddress((void**)&xconv,  g_xconv);
    cudaGetSymbolAddress((void**)&params, g_params);
    cudaGetSymbolAddress((void**)&P,      g_P);
    cudaGetSymbolAddress((void**)&hend,   g_hend);
    cudaGetSymbolAddress((void**)&hini,   g_hini);
    cudaGetSymbolAddress((void**)&xh,     g_xh);
    cudaGetSymbolAddress((void**)&w1hi,   g_w1hi);
    cudaGetSymbolAddress((void**)&w1lo,   g_w1lo);
    cudaGetSymbolAddress((void**)&w2hi,   g_w2hi);
    cudaGetSymbolAddress((void**)&w2lo,   g_w2lo);
    cudaGetSymbolAddress((void**)&yh,     g_yh);

    cudaFuncSetAttribute(gemm_fp16_2t,
                         cudaFuncAttributeMaxDynamicSharedMemorySize, GEMM_SMEM);

    // 0) merged precision prep
    prep_kernel<<<(N_PREP + 255)/256, 256>>>(x, in_proj_w, out_proj_w,
                                             xh, w1hi, w1lo, w2hi, w2lo);

    // 1) in_proj: (4096,1024) @ (2048,1024)^T -> (4096,2048)
    {
        dim3 grid(E2 / 128, MROWS / 128);
        gemm_fp16_2t<<<grid, 256, GEMM_SMEM>>>(xh, w1hi, w1lo, xz, MROWS, E2, DD);
    }
    // 2) depthwise conv + SiLU
    conv_silu_kernel<<<(MROWS*DD/4 + 255)/256, 256>>>(xz, conv_w, conv_b, xconv);
    // 3) x_proj (tiled)
    {
        dim3 blk(33, 8);
        xproj_tiled<<<MROWS / 32, blk>>>(xconv, x_proj_w, params);
    }
    // 4) chunked selective scan
    scanA_kernel<<<BB * NCH * (DD/128), 128>>>(params, xconv, dt_proj_w, dt_proj_b, A_log, P, hend);
    scanB_kernel<<<(BB*DD + 255)/256, 256>>>(P, hend, hini);
    scanC_kernel<<<BB * NCH * (DD/128), 128>>>(params, xconv, xz, dt_proj_w, dt_proj_b, A_log, hini, yh);
    // 5) out_proj: (4096,1024) @ (1024,1024)^T -> (4096,1024)
    {
        dim3 grid(DD / 128, MROWS / 128);
        gemm_fp16_2t<<<grid, 256, GEMM_SMEM>>>(yh, w2hi, w2lo, out, MROWS, DD, DD);
    }
}

// round 13
// speedup vs baseline: 1.4670x; 1.0408x over previous
#include <cuda_runtime.h>
#include <cuda_fp16.h>
#include <cstdint>

// Problem dims (fixed by the reference)
#define BB 2
#define TT 2048
#define DD 1024
#define NN 16
#define DCONV 4
#define MROWS (BB*TT)          // 4096
#define E2 (2*DD)              // 2048
#define NPAR (2*NN+1)          // 33
#define NCH 32                 // scan chunks
#define CHL (TT/NCH)           // 64 steps per chunk
#define KSPL 4                 // x_proj K-split factor
#define KCH (DD/KSPL)          // 256

// ---------- scratch (static device allocations only) ----------
__device__ float g_xz[(size_t)MROWS * E2];        // in_proj output (x_in | z)
__device__ float g_xconv[(size_t)MROWS * DD];     // conv+silu output
__device__ float g_params[(size_t)KSPL * MROWS * NPAR];  // x_proj partials
__device__ __half g_xh [(size_t)MROWS * DD];      // x in fp16
__device__ __half g_w1hi[(size_t)E2 * DD], g_w1lo[(size_t)E2 * DD];
__device__ __half g_w2hi[(size_t)DD * DD], g_w2lo[(size_t)DD * DD];
__device__ __half g_yh [(size_t)MROWS * DD];      // scan output in fp16
__device__ float g_P   [(size_t)BB * NCH * NN * DD];
__device__ float g_hend[(size_t)BB * NCH * NN * DD];
__device__ float g_hini[(size_t)BB * NCH * NN * DD];

// =====================================================================
// Merged precision prep:
//  range0: x -> fp16   range1: w1 -> fp16 hi/lo   range2: w2 -> fp16 hi/lo
// =====================================================================
#define N_X4  (MROWS*DD/4)
#define N_W14 (E2*DD/4)
#define N_W24 (DD*DD/4)
#define N_PREP (N_X4 + N_W14 + N_W24)

__device__ __forceinline__ void split_one(float4 v, __half* hi, __half* lo, int i) {
    __half hx = __float2half_rn(v.x);
    __half hy = __float2half_rn(v.y);
    __half hz = __float2half_rn(v.z);
    __half hw = __float2half_rn(v.w);
    __half2 h01; h01.x = hx; h01.y = hy;
    __half2 h23; h23.x = hz; h23.y = hw;
    ((__half2*)hi)[i*2]   = h01;
    ((__half2*)hi)[i*2+1] = h23;
    __half2 l01, l23;
    l01.x = __float2half_rn(v.x - __half2float(hx));
    l01.y = __float2half_rn(v.y - __half2float(hy));
    l23.x = __float2half_rn(v.z - __half2float(hz));
    l23.y = __float2half_rn(v.w - __half2float(hw));
    ((__half2*)lo)[i*2]   = l01;
    ((__half2*)lo)[i*2+1] = l23;
}

__global__ void prep_kernel(const float* __restrict__ x,
                            const float* __restrict__ w1,
                            const float* __restrict__ w2,
                            __half* __restrict__ xh,
                            __half* __restrict__ w1hi, __half* __restrict__ w1lo,
                            __half* __restrict__ w2hi, __half* __restrict__ w2lo)
{
    int i = blockIdx.x * blockDim.x + threadIdx.x;
    if (i < N_X4) {
        float4 v = ((const float4*)x)[i];
        ((__half2*)xh)[i*2]   = __floats2half2_rn(v.x, v.y);
        ((__half2*)xh)[i*2+1] = __floats2half2_rn(v.z, v.w);
    } else if (i < N_X4 + N_W14) {
        int j = i - N_X4;
        split_one(((const float4*)w1)[j], w1hi, w1lo, j);
    } else if (i < N_PREP) {
        int j = i - N_X4 - N_W14;
        split_one(((const float4*)w2)[j], w2hi, w2lo, j);
    }
}

// =====================================================================
// Tensor-core GEMM, fp16 2-term (proven R7/R8 config, unchanged).
// =====================================================================
#define GLDA 40
#define ARR_B  (128*GLDA*2)
#define STAGE_B (3*ARR_B)
#define NSTAGE 3
#define GEMM_SMEM (NSTAGE*STAGE_B)

__device__ __forceinline__ void mma16816h(float* c, const uint32_t* a, const uint32_t* b) {
    asm volatile(
        "mma.sync.aligned.m16n8k16.row.col.f32.f16.f16.f32 "
        "{%0,%1,%2,%3}, {%4,%5,%6,%7}, {%8,%9}, {%0,%1,%2,%3};"
        : "+f"(c[0]), "+f"(c[1]), "+f"(c[2]), "+f"(c[3])
        : "r"(a[0]), "r"(a[1]), "r"(a[2]), "r"(a[3]), "r"(b[0]), "r"(b[1]));
}
__device__ __forceinline__ void ldm4(uint32_t* r, uint32_t addr) {
    asm volatile(
        "ldmatrix.sync.aligned.m8n8.x4.shared.b16 {%0,%1,%2,%3}, [%4];"
        : "=r"(r[0]), "=r"(r[1]), "=r"(r[2]), "=r"(r[3]) : "r"(addr));
}
__device__ __forceinline__ void cpasync16(uint32_t dst, const void* src) {
    asm volatile("cp.async.cg.shared.global [%0], [%1], 16;" :: "r"(dst), "l"(src));
}

__global__ __launch_bounds__(256, 2) void gemm_fp16_2t(
    const __half* __restrict__ A,
    const __half* __restrict__ Whi, const __half* __restrict__ Wlo,
    float* __restrict__ C, int M, int N, int K)
{
    extern __shared__ __align__(16) char dsm[];

    const int tid  = threadIdx.x;
    const int lane = tid & 31;
    const int warp = tid >> 5;
    const int wm   = warp >> 2;
    const int wn   = warp & 3;
    const int brow = blockIdx.y * 128;
    const int bcol = blockIdx.x * 128;

    float acc[4][4][4];
    #pragma unroll
    for (int i = 0; i < 4; i++)
        #pragma unroll
        for (int j = 0; j < 4; j++)
            #pragma unroll
            for (int k = 0; k < 4; k++) acc[i][j][k] = 0.f;

    const uint32_t sbase = (uint32_t)__cvta_generic_to_shared(dsm);

    const __half* srcs[3];
    srcs[0] = A   + (size_t)(brow) * K;
    srcs[1] = Whi + (size_t)(bcol) * K;
    srcs[2] = Wlo + (size_t)(bcol) * K;

    uint32_t offA[4];
    #pragma unroll
    for (int mi = 0; mi < 4; mi++) {
        int row = wm * 64 + mi * 16 + (lane & 15);
        int ko  = (lane >> 4) * 8;
        offA[mi] = (uint32_t)(row * GLDA + ko) * 2u;
    }
    uint32_t offB[2];
    #pragma unroll
    for (int ni2 = 0; ni2 < 2; ni2++) {
        int row = wn * 32 + ni2 * 16 + (lane & 7) + ((lane >> 4) << 3);
        int ko  = ((lane >> 3) & 1) * 8;
        offB[ni2] = (uint32_t)(row * GLDA + ko) * 2u;
    }

    const int NK = K / 32;

    auto load_slab = [&](int slab, int stage) {
        const uint32_t stB = sbase + (uint32_t)stage * STAGE_B;
        #pragma unroll
        for (int arr = 0; arr < 3; arr++) {
            const __half* sp = srcs[arr] + slab * 32;
            #pragma unroll
            for (int j = 0; j < 2; j++) {
                int idx = tid + j * 256;
                int row = idx >> 2;
                int kc  = idx & 3;
                uint32_t dst = stB + (uint32_t)arr * ARR_B + (uint32_t)(row * GLDA + kc * 8) * 2u;
                cpasync16(dst, sp + (size_t)row * K + kc * 8);
            }
        }
        asm volatile("cp.async.commit_group;");
    };

    load_slab(0, 0);
    load_slab(1, 1);

    for (int kt = 0; kt < NK; kt++) {
        const int stage = kt % 3;
        if (kt < NK - 1) asm volatile("cp.async.wait_group 1;");
        else             asm volatile("cp.async.wait_group 0;");
        __syncthreads();

        if (kt + 2 < NK) load_slab(kt + 2, (kt + 2) % 3);

        const uint32_t stA   = sbase + (uint32_t)stage * STAGE_B;
        const uint32_t stWhi = stA + ARR_B;
        const uint32_t stWlo = stA + 2 * ARR_B;

        #pragma unroll
        for (int ks = 0; ks < 2; ks++) {
            const uint32_t kadd = (uint32_t)(ks * 32);
            uint32_t a[4][4], bhi[2][4], blo[2][4];
            #pragma unroll
            for (int ni2 = 0; ni2 < 2; ni2++) {
                ldm4(bhi[ni2], stWhi + offB[ni2] + kadd);
                ldm4(blo[ni2], stWlo + offB[ni2] + kadd);
            }
            #pragma unroll
            for (int mi = 0; mi < 4; mi++)
                ldm4(a[mi], stA + offA[mi] + kadd);
            #pragma unroll
            for (int mi = 0; mi < 4; mi++) {
                #pragma unroll
                for (int nf = 0; nf < 4; nf++) {
                    const int ni2 = nf >> 1;
                    const int s   = (nf & 1) * 2;
                    uint32_t bh[2] = { bhi[ni2][s], bhi[ni2][s + 1] };
                    uint32_t bl[2] = { blo[ni2][s], blo[ni2][s + 1] };
                    mma16816h(acc[mi][nf], a[mi], bh);
                    mma16816h(acc[mi][nf], a[mi], bl);
                }
            }
        }
    }

    const int gid = lane >> 2;
    const int tig = lane & 3;
    #pragma unroll
    for (int mi = 0; mi < 4; mi++) {
        #pragma unroll
        for (int nf = 0; nf < 4; nf++) {
            int row = brow + wm * 64 + mi * 16 + gid;
            int col = bcol + wn * 32 + nf * 8 + tig * 2;
            *(float2*)(C + (size_t)row * N + col) =
                make_float2(acc[mi][nf][0], acc[mi][nf][1]);
            *(float2*)(C + (size_t)(row + 8) * N + col) =
                make_float2(acc[mi][nf][2], acc[mi][nf][3]);
        }
    }
}

// =====================================================================
// Depthwise causal conv (width 4) + bias + SiLU, float4-vectorized
// =====================================================================
__global__ void conv_silu_kernel(const float* __restrict__ xz,
                                 const float* __restrict__ cw,
                                 const float* __restrict__ cb,
                                 float* __restrict__ xconv)
{
    int idx = blockIdx.x * blockDim.x + threadIdx.x;
    if (idx >= MROWS * DD / 4) return;
    int d4 = idx & (DD / 4 - 1);
    int bt = idx >> 8;
    int t  = bt & (TT - 1);
    int b  = bt >> 11;

    float4 cw0 = ((const float4*)cw)[d4 * 4 + 0];
    float4 cw1 = ((const float4*)cw)[d4 * 4 + 1];
    float4 cw2 = ((const float4*)cw)[d4 * 4 + 2];
    float4 cw3 = ((const float4*)cw)[d4 * 4 + 3];
    float4 acc = ((const float4*)cb)[d4];

    #pragma unroll
    for (int j = 0; j < DCONV; j++) {
        int tt = t - (DCONV - 1) + j;
        if (tt >= 0) {
            float4 xv = *(const float4*)(xz + (size_t)(b * TT + tt) * E2 + d4 * 4);
            float w0 = (&cw0.x)[j], w1 = (&cw1.x)[j], w2 = (&cw2.x)[j], w3 = (&cw3.x)[j];
            acc.x = fmaf(xv.x, w0, acc.x);
            acc.y = fmaf(xv.y, w1, acc.y);
            acc.z = fmaf(xv.z, w2, acc.z);
            acc.w = fmaf(xv.w, w3, acc.w);
        }
    }
    acc.x = acc.x / (1.0f + __expf(-acc.x));
    acc.y = acc.y / (1.0f + __expf(-acc.y));
    acc.z = acc.z / (1.0f + __expf(-acc.z));
    acc.w = acc.w / (1.0f + __expf(-acc.w));
    *(float4*)(xconv + (size_t)bt * DD + d4 * 4) = acc;
}

// =====================================================================
// K-split tiled x_proj: grid (128 rowblocks, KSPL), block (33,8).
// Block (rx, ks) computes partial dot over K chunk ks for 32 rows.
// params_part[ks][row][e]; summed during scan staging.
// =====================================================================
__global__ void xproj_tiled(const float* __restrict__ xconv,
                            const float* __restrict__ W,
                            float* __restrict__ pp)
{
    __shared__ float sx[32][68];
    const int e  = threadIdx.x;   // 0..32
    const int rg = threadIdx.y;   // 0..7
    const int flat = rg * 33 + e;
    const int row0 = blockIdx.x * 32;
    const int kbase = blockIdx.y * KCH;

    float acc[4] = {0.f, 0.f, 0.f, 0.f};

    for (int k0 = kbase; k0 < kbase + KCH; k0 += 64) {
        __syncthreads();
        for (int c = flat; c < 512; c += 264) {
            int ri = c >> 4;
            int k4 = c & 15;
            float4 v = *(const float4*)(xconv + (size_t)(row0 + ri) * DD + k0 + k4 * 4);
            *(float4*)&sx[ri][k4 * 4] = v;
        }
        __syncthreads();
        const float* wrow = W + (size_t)e * DD + k0;
        #pragma unroll
        for (int k4 = 0; k4 < 16; k4++) {
            float4 w4 = *(const float4*)(wrow + k4 * 4);
            #pragma unroll
            for (int j = 0; j < 4; j++) {
                const float* sxr = sx[rg * 4 + j];
                acc[j] = fmaf(sxr[k4*4+0], w4.x, acc[j]);
                acc[j] = fmaf(sxr[k4*4+1], w4.y, acc[j]);
                acc[j] = fmaf(sxr[k4*4+2], w4.z, acc[j]);
                acc[j] = fmaf(sxr[k4*4+3], w4.w, acc[j]);
            }
        }
    }
    float* base = pp + (size_t)blockIdx.y * MROWS * NPAR;
    #pragma unroll
    for (int j = 0; j < 4; j++)
        base[(size_t)(row0 + rg * 4 + j) * NPAR + e] = acc[j];
}

// =====================================================================
// Scan pass A. Chunk params staged in padded smem, summing the KSPL
// partials during staging. Fast exp-chain path when A_log = log(1..N).
// =====================================================================
#define SPQ (CHL*NPAR/4)              // 528 float4 per chunk
#define PSTR ((size_t)MROWS*NPAR/4)   // partial stride in float4

__global__ __launch_bounds__(128) void scanA_kernel(const float* __restrict__ params,
                                                    const float* __restrict__ xconv,
                                                    const float* __restrict__ dtw,
                                                    const float* __restrict__ dtb,
                                                    const float* __restrict__ A_log,
                                                    float* __restrict__ Pout,
                                                    float* __restrict__ hend)
{
    __shared__ float sp[CHL][36];
    const int dg = blockIdx.x & 7;
    const int c  = (blockIdx.x >> 3) & (NCH - 1);
    const int b  = blockIdx.x >> 8;
    const int d  = dg * 128 + threadIdx.x;
    const size_t rowbase = (size_t)b * TT + (size_t)c * CHL;

    {
        const float4* src = (const float4*)(params + rowbase * NPAR);
        for (int i = threadIdx.x; i < SPQ; i += 128) {
            float4 v0 = src[i];
            float4 v1 = src[i + PSTR];
            float4 v2 = src[i + 2 * PSTR];
            float4 v3 = src[i + 3 * PSTR];
            float4 v = make_float4((v0.x + v1.x) + (v2.x + v3.x),
                                   (v0.y + v1.y) + (v2.y + v3.y),
                                   (v0.z + v1.z) + (v2.z + v3.z),
                                   (v0.w + v1.w) + (v2.w + v3.w));
            int e = i * 4;
            #pragma unroll
            for (int j = 0; j < 4; j++) {
                int ee = e + j;
                sp[ee / NPAR][ee % NPAR] = (&v.x)[j];
            }
        }
    }

    float a[NN];
    #pragma unroll
    for (int n = 0; n < NN; n++)
        a[n] = -expf(A_log[(size_t)d * NN + n]);
    const float w    = dtw[d];
    const float bias = dtb[d];

    bool fast = true;
    #pragma unroll
    for (int n = 1; n < NN; n++)
        fast = fast && (fabsf(a[n] - (float)(n + 1) * a[0]) <= 1e-4f * fabsf(a[n]) + 1e-12f);

    float h[NN], P[NN];
    #pragma unroll
    for (int n = 0; n < NN; n++) { h[n] = 0.f; P[n] = 1.f; }

    __syncthreads();

    if (fast) {
        const float a0 = a[0];
        for (int t = 0; t < CHL; t++) {
            float pv[16];
            *(float4*)&pv[0]  = *(const float4*)&sp[t][0];
            *(float4*)&pv[4]  = *(const float4*)&sp[t][4];
            *(float4*)&pv[8]  = *(const float4*)&sp[t][8];
            *(float4*)&pv[12] = *(const float4*)&sp[t][12];
            float v  = fmaf(sp[t][32], w, bias);
            float dt = (v > 20.f) ? v : __logf(1.0f + __expf(v));
            float dtx = dt * xconv[(rowbase + t) * DD + d];
            float q = __expf(dt * a0);
            float e = q;
            #pragma unroll
            for (int n = 0; n < NN; n++) {
                h[n] = fmaf(e, h[n], dtx * pv[n]);
                P[n] *= e;
                e *= q;
            }
        }
    } else {
        for (int t = 0; t < CHL; t++) {
            float pv[16];
            *(float4*)&pv[0]  = *(const float4*)&sp[t][0];
            *(float4*)&pv[4]  = *(const float4*)&sp[t][4];
            *(float4*)&pv[8]  = *(const float4*)&sp[t][8];
            *(float4*)&pv[12] = *(const float4*)&sp[t][12];
            float v  = fmaf(sp[t][32], w, bias);
            float dt = (v > 20.f) ? v : __logf(1.0f + __expf(v));
            float dtx = dt * xconv[(rowbase + t) * DD + d];
            #pragma unroll
            for (int n = 0; n < NN; n++) {
                float e = __expf(dt * a[n]);
                h[n] = fmaf(e, h[n], dtx * pv[n]);
                P[n] *= e;
            }
        }
    }
    const size_t o = ((size_t)(b * NCH + c) * NN) * DD + d;
    #pragma unroll
    for (int n = 0; n < NN; n++) {
        hend[o + (size_t)n * DD] = h[n];
        Pout[o + (size_t)n * DD] = P[n];
    }
}

// =====================================================================
// Pass B: sequential chunk combine.
// =====================================================================
__global__ void scanB_kernel(const float* __restrict__ P,
                             const float* __restrict__ hend,
                             float* __restrict__ hini)
{
    int gid = blockIdx.x * blockDim.x + threadIdx.x;
    if (gid >= BB * DD) return;
    int d = gid & (DD - 1);
    int b = gid >> 10;

    float h[NN];
    #pragma unroll
    for (int n = 0; n < NN; n++) h[n] = 0.f;

    for (int c = 0; c < NCH; c++) {
        const size_t o = ((size_t)(b * NCH + c) * NN) * DD + d;
        #pragma unroll
        for (int n = 0; n < NN; n++) {
            hini[o + (size_t)n * DD] = h[n];
            h[n] = fmaf(P[o + (size_t)n * DD], h[n], hend[o + (size_t)n * DD]);
        }
    }
}

// =====================================================================
// Pass C: re-run chunks from h_init; emit y=(h·C)*silu(z) as fp16.
// =====================================================================
__global__ __launch_bounds__(128) void scanC_kernel(const float* __restrict__ params,
                                                    const float* __restrict__ xconv,
                                                    const float* __restrict__ xz,
                                                    const float* __restrict__ dtw,
                                                    const float* __restrict__ dtb,
                                                    const float* __restrict__ A_log,
                                                    const float* __restrict__ hini,
                                                    __half* __restrict__ yh)
{
    __shared__ float sp[CHL][36];
    const int dg = blockIdx.x & 7;
    const int c  = (blockIdx.x >> 3) & (NCH - 1);
    const int b  = blockIdx.x >> 8;
    const int d  = dg * 128 + threadIdx.x;
    const size_t rowbase = (size_t)b * TT + (size_t)c * CHL;

    {
        const float4* src = (const float4*)(params + rowbase * NPAR);
        for (int i = threadIdx.x; i < SPQ; i += 128) {
            float4 v0 = src[i];
            float4 v1 = src[i + PSTR];
            float4 v2 = src[i + 2 * PSTR];
            float4 v3 = src[i + 3 * PSTR];
            float4 v = make_float4((v0.x + v1.x) + (v2.x + v3.x),
                                   (v0.y + v1.y) + (v2.y + v3.y),
                                   (v0.z + v1.z) + (v2.z + v3.z),
                                   (v0.w + v1.w) + (v2.w + v3.w));
            int e = i * 4;
            #pragma unroll
            for (int j = 0; j < 4; j++) {
                int ee = e + j;
                sp[ee / NPAR][ee % NPAR] = (&v.x)[j];
            }
        }
    }

    float a[NN];
    #pragma unroll
    for (int n = 0; n < NN; n++)
        a[n] = -expf(A_log[(size_t)d * NN + n]);
    const float w    = dtw[d];
    const float bias = dtb[d];

    bool fast = true;
    #pragma unroll
    for (int n = 1; n < NN; n++)
        fast = fast && (fabsf(a[n] - (float)(n + 1) * a[0]) <= 1e-4f * fabsf(a[n]) + 1e-12f);

    float h[NN];
    const size_t o = ((size_t)(b * NCH + c) * NN) * DD + d;
    #pragma unroll
    for (int n = 0; n < NN; n++) h[n] = hini[o + (size_t)n * DD];

    __syncthreads();

    if (fast) {
        const float a0 = a[0];
        for (int t = 0; t < CHL; t++) {
            const size_t r = rowbase + t;
            float pv[16], cv[16];
            *(float4*)&pv[0]  = *(const float4*)&sp[t][0];
            *(float4*)&pv[4]  = *(const float4*)&sp[t][4];
            *(float4*)&pv[8]  = *(const float4*)&sp[t][8];
            *(float4*)&pv[12] = *(const float4*)&sp[t][12];
            *(float4*)&cv[0]  = *(const float4*)&sp[t][16];
            *(float4*)&cv[4]  = *(const float4*)&sp[t][20];
            *(float4*)&cv[8]  = *(const float4*)&sp[t][24];
            *(float4*)&cv[12] = *(const float4*)&sp[t][28];
            float v  = fmaf(sp[t][32], w, bias);
            float dt = (v > 20.f) ? v : __logf(1.0f + __expf(v));
            float dtx = dt * xconv[r * DD + d];
            float zv  = xz[r * E2 + DD + d];
            float q = __expf(dt * a0);
            float e = q;
            float yv = 0.f;
            #pragma unroll
            for (int n = 0; n < NN; n++) {
                h[n] = fmaf(e, h[n], dtx * pv[n]);
                yv = fmaf(h[n], cv[n], yv);
                e *= q;
            }
            float sil = zv / (1.0f + __expf(-zv));
            yh[r * DD + d] = __float2half_rn(yv * sil);
        }
    } else {
        for (int t = 0; t < CHL; t++) {
            const size_t r = rowbase + t;
            float pv[16], cv[16];
            *(float4*)&pv[0]  = *(const float4*)&sp[t][0];
            *(float4*)&pv[4]  = *(const float4*)&sp[t][4];
            *(float4*)&pv[8]  = *(const float4*)&sp[t][8];
            *(float4*)&pv[12] = *(const float4*)&sp[t][12];
            *(float4*)&cv[0]  = *(const float4*)&sp[t][16];
            *(float4*)&cv[4]  = *(const float4*)&sp[t][20];
            *(float4*)&cv[8]  = *(const float4*)&sp[t][24];
            *(float4*)&cv[12] = *(const float4*)&sp[t][28];
            float v  = fmaf(sp[t][32], w, bias);
            float dt = (v > 20.f) ? v : __logf(1.0f + __expf(v));
            float dtx = dt * xconv[r * DD + d];
            float zv  = xz[r * E2 + DD + d];
            float yv = 0.f;
            #pragma unroll
            for (int n = 0; n < NN; n++) {
                float e = __expf(dt * a[n]);
                h[n] = fmaf(e, h[n], dtx * pv[n]);
                yv = fmaf(h[n], cv[n], yv);
            }
            float sil = zv / (1.0f + __expf(-zv));
            yh[r * DD + d] = __float2half_rn(yv * sil);
        }
    }
}

// =====================================================================
// launch
// =====================================================================
extern "C" void kernel_launch(void* const* d_in, const int* in_sizes, int n_in,
                              void* d_out, int out_size)
{
    const float* x         = (const float*)d_in[0];
    const float* in_proj_w = (const float*)d_in[1];
    const float* conv_w    = (const float*)d_in[2];
    const float* conv_b    = (const float*)d_in[3];
    const float* x_proj_w  = (const float*)d_in[4];
    const float* dt_proj_w = (const float*)d_in[5];
    const float* dt_proj_b = (const float*)d_in[6];
    const float* A_log     = (const float*)d_in[7];
    const float* out_proj_w= (const float*)d_in[8];
    float* out = (float*)d_out;

    float *xz, *xconv, *params, *P, *hend, *hini;
    __half *xh, *w1hi, *w1lo, *w2hi, *w2lo, *yh;
    cudaGetSymbolAddress((void**)&xz,     g_xz);
    cudaGetSymbolAddress((void**)&xconv,  g_xconv);
    cudaGetSymbolAddress((void**)&params, g_params);
    cudaGetSymbolAddress((void**)&P,      g_P);
    cudaGetSymbolAddress((void**)&hend,   g_hend);
    cudaGetSymbolAddress((void**)&hini,   g_hini);
    cudaGetSymbolAddress((void**)&xh,     g_xh);
    cudaGetSymbolAddress((void**)&w1hi,   g_w1hi);
    cudaGetSymbolAddress((void**)&w1lo,   g_w1lo);
    cudaGetSymbolAddress((void**)&w2hi,   g_w2hi);
    cudaGetSymbolAddress((void**)&w2lo,   g_w2lo);
    cudaGetSymbolAddress((void**)&yh,     g_yh);

    cudaFuncSetAttribute(gemm_fp16_2t,
                         cudaFuncAttributeMaxDynamicSharedMemorySize, GEMM_SMEM);

    // 0) merged precision prep
    prep_kernel<<<(N_PREP + 255)/256, 256>>>(x, in_proj_w, out_proj_w,
                                             xh, w1hi, w1lo, w2hi, w2lo);

    // 1) in_proj
    {
        dim3 grid(E2 / 128, MROWS / 128);
        gemm_fp16_2t<<<grid, 256, GEMM_SMEM>>>(xh, w1hi, w1lo, xz, MROWS, E2, DD);
    }
    // 2) depthwise conv + SiLU
    conv_silu_kernel<<<(MROWS*DD/4 + 255)/256, 256>>>(xz, conv_w, conv_b, xconv);
    // 3) x_proj (K-split tiled)
    {
        dim3 grid(MROWS / 32, KSPL);
        dim3 blk(33, 8);
        xproj_tiled<<<grid, blk>>>(xconv, x_proj_w, params);
    }
    // 4) chunked selective scan
    scanA_kernel<<<BB * NCH * (DD/128), 128>>>(params, xconv, dt_proj_w, dt_proj_b, A_log, P, hend);
    scanB_kernel<<<(BB*DD + 255)/256, 256>>>(P, hend, hini);
    scanC_kernel<<<BB * NCH * (DD/128), 128>>>(params, xconv, xz, dt_proj_w, dt_proj_b, A_log, hini, yh);
    // 5) out_proj
    {
        dim3 grid(DD / 128, MROWS / 128);
        gemm_fp16_2t<<<grid, 256, GEMM_SMEM>>>(yh, w2hi, w2lo, out, MROWS, DD, DD);
    }
}

// round 15
// speedup vs baseline: 1.6346x; 1.1143x over previous
#include <cuda_runtime.h>
#include <cuda_fp16.h>
#include <cstdint>

// Problem dims (fixed by the reference)
#define BB 2
#define TT 2048
#define DD 1024
#define NN 16
#define DCONV 4
#define MROWS (BB*TT)          // 4096
#define E2 (2*DD)              // 2048
#define NPAR (2*NN+1)          // 33
#define NPAD 64                // padded x_proj output dim
#define NCH 32                 // scan chunks
#define CHL (TT/NCH)           // 64 steps per chunk
#define KSPL 4                 // x_proj K-split factor
#define KCH (DD/KSPL)          // 256

// ---------- scratch (static device allocations only) ----------
__device__ float g_xz[(size_t)MROWS * E2];        // in_proj output (x_in | z)
__device__ float g_xconv[(size_t)MROWS * DD];     // conv+silu output (fp32, scan use)
__device__ float g_params[(size_t)KSPL * MROWS * NPAR];  // x_proj partials
__device__ __half g_xh [(size_t)MROWS * DD];      // x in fp16
__device__ __half g_w1hi[(size_t)E2 * DD], g_w1lo[(size_t)E2 * DD];
__device__ __half g_w2hi[(size_t)DD * DD], g_w2lo[(size_t)DD * DD];
__device__ __half g_xchi[(size_t)MROWS * DD], g_xclo[(size_t)MROWS * DD]; // xconv hi/lo
__device__ __half g_wxhi[(size_t)NPAD * DD], g_wxlo[(size_t)NPAD * DD];   // padded x_proj_w hi/lo
__device__ __half g_yh [(size_t)MROWS * DD];      // scan output in fp16
__device__ float g_P   [(size_t)BB * NCH * NN * DD];
__device__ float g_hend[(size_t)BB * NCH * NN * DD];
__device__ float g_hini[(size_t)BB * NCH * NN * DD];

// =====================================================================
// Merged precision prep:
//  range0: x -> fp16           range1: w1 -> fp16 hi/lo
//  range2: w2 -> fp16 hi/lo    range3: x_proj_w -> padded fp16 hi/lo
// =====================================================================
#define N_X4   (MROWS*DD/4)
#define N_W14  (E2*DD/4)
#define N_W24  (DD*DD/4)
#define N_WX4  (NPAD*DD/4)          // padded slots
#define N_WXR  (NPAR*DD/4)          // real x_proj_w float4 count (8448)
#define N_PREP (N_X4 + N_W14 + N_W24 + N_WX4)

__device__ __forceinline__ void split_one(float4 v, __half* hi, __half* lo, int i) {
    __half hx = __float2half_rn(v.x);
    __half hy = __float2half_rn(v.y);
    __half hz = __float2half_rn(v.z);
    __half hw = __float2half_rn(v.w);
    __half2 h01; h01.x = hx; h01.y = hy;
    __half2 h23; h23.x = hz; h23.y = hw;
    ((__half2*)hi)[i*2]   = h01;
    ((__half2*)hi)[i*2+1] = h23;
    __half2 l01, l23;
    l01.x = __float2half_rn(v.x - __half2float(hx));
    l01.y = __float2half_rn(v.y - __half2float(hy));
    l23.x = __float2half_rn(v.z - __half2float(hz));
    l23.y = __float2half_rn(v.w - __half2float(hw));
    ((__half2*)lo)[i*2]   = l01;
    ((__half2*)lo)[i*2+1] = l23;
}

__global__ void prep_kernel(const float* __restrict__ x,
                            const float* __restrict__ w1,
                            const float* __restrict__ w2,
                            const float* __restrict__ wx,
                            __half* __restrict__ xh,
                            __half* __restrict__ w1hi, __half* __restrict__ w1lo,
                            __half* __restrict__ w2hi, __half* __restrict__ w2lo,
                            __half* __restrict__ wxhi, __half* __restrict__ wxlo)
{
    int i = blockIdx.x * blockDim.x + threadIdx.x;
    if (i < N_X4) {
        float4 v = ((const float4*)x)[i];
        ((__half2*)xh)[i*2]   = __floats2half2_rn(v.x, v.y);
        ((__half2*)xh)[i*2+1] = __floats2half2_rn(v.z, v.w);
    } else if (i < N_X4 + N_W14) {
        int j = i - N_X4;
        split_one(((const float4*)w1)[j], w1hi, w1lo, j);
    } else if (i < N_X4 + N_W14 + N_W24) {
        int j = i - N_X4 - N_W14;
        split_one(((const float4*)w2)[j], w2hi, w2lo, j);
    } else if (i < N_PREP) {
        int j = i - N_X4 - N_W14 - N_W24;
        float4 v = (j < N_WXR) ? ((const float4*)wx)[j]
                               : make_float4(0.f, 0.f, 0.f, 0.f);
        split_one(v, wxhi, wxlo, j);
    }
}

// =====================================================================
// Tensor-core GEMM, fp16 2-term (proven R7/R8 config, unchanged).
// =====================================================================
#define GLDA 40
#define ARR_B  (128*GLDA*2)
#define STAGE_B (3*ARR_B)
#define NSTAGE 3
#define GEMM_SMEM (NSTAGE*STAGE_B)

__device__ __forceinline__ void mma16816h(float* c, const uint32_t* a, const uint32_t* b) {
    asm volatile(
        "mma.sync.aligned.m16n8k16.row.col.f32.f16.f16.f32 "
        "{%0,%1,%2,%3}, {%4,%5,%6,%7}, {%8,%9}, {%0,%1,%2,%3};"
        : "+f"(c[0]), "+f"(c[1]), "+f"(c[2]), "+f"(c[3])
        : "r"(a[0]), "r"(a[1]), "r"(a[2]), "r"(a[3]), "r"(b[0]), "r"(b[1]));
}
__device__ __forceinline__ void ldm4(uint32_t* r, uint32_t addr) {
    asm volatile(
        "ldmatrix.sync.aligned.m8n8.x4.shared.b16 {%0,%1,%2,%3}, [%4];"
        : "=r"(r[0]), "=r"(r[1]), "=r"(r[2]), "=r"(r[3]) : "r"(addr));
}
__device__ __forceinline__ void cpasync16(uint32_t dst, const void* src) {
    asm volatile("cp.async.cg.shared.global [%0], [%1], 16;" :: "r"(dst), "l"(src));
}

__global__ __launch_bounds__(256, 2) void gemm_fp16_2t(
    const __half* __restrict__ A,
    const __half* __restrict__ Whi, const __half* __restrict__ Wlo,
    float* __restrict__ C, int M, int N, int K)
{
    extern __shared__ __align__(16) char dsm[];

    const int tid  = threadIdx.x;
    const int lane = tid & 31;
    const int warp = tid >> 5;
    const int wm   = warp >> 2;
    const int wn   = warp & 3;
    const int brow = blockIdx.y * 128;
    const int bcol = blockIdx.x * 128;

    float acc[4][4][4];
    #pragma unroll
    for (int i = 0; i < 4; i++)
        #pragma unroll
        for (int j = 0; j < 4; j++)
            #pragma unroll
            for (int k = 0; k < 4; k++) acc[i][j][k] = 0.f;

    const uint32_t sbase = (uint32_t)__cvta_generic_to_shared(dsm);

    const __half* srcs[3];
    srcs[0] = A   + (size_t)(brow) * K;
    srcs[1] = Whi + (size_t)(bcol) * K;
    srcs[2] = Wlo + (size_t)(bcol) * K;

    uint32_t offA[4];
    #pragma unroll
    for (int mi = 0; mi < 4; mi++) {
        int row = wm * 64 + mi * 16 + (lane & 15);
        int ko  = (lane >> 4) * 8;
        offA[mi] = (uint32_t)(row * GLDA + ko) * 2u;
    }
    uint32_t offB[2];
    #pragma unroll
    for (int ni2 = 0; ni2 < 2; ni2++) {
        int row = wn * 32 + ni2 * 16 + (lane & 7) + ((lane >> 4) << 3);
        int ko  = ((lane >> 3) & 1) * 8;
        offB[ni2] = (uint32_t)(row * GLDA + ko) * 2u;
    }

    const int NK = K / 32;

    auto load_slab = [&](int slab, int stage) {
        const uint32_t stB = sbase + (uint32_t)stage * STAGE_B;
        #pragma unroll
        for (int arr = 0; arr < 3; arr++) {
            const __half* sp = srcs[arr] + slab * 32;
            #pragma unroll
            for (int j = 0; j < 2; j++) {
                int idx = tid + j * 256;
                int row = idx >> 2;
                int kc  = idx & 3;
                uint32_t dst = stB + (uint32_t)arr * ARR_B + (uint32_t)(row * GLDA + kc * 8) * 2u;
                cpasync16(dst, sp + (size_t)row * K + kc * 8);
            }
        }
        asm volatile("cp.async.commit_group;");
    };

    load_slab(0, 0);
    load_slab(1, 1);

    for (int kt = 0; kt < NK; kt++) {
        const int stage = kt % 3;
        if (kt < NK - 1) asm volatile("cp.async.wait_group 1;");
        else             asm volatile("cp.async.wait_group 0;");
        __syncthreads();

        if (kt + 2 < NK) load_slab(kt + 2, (kt + 2) % 3);

        const uint32_t stA   = sbase + (uint32_t)stage * STAGE_B;
        const uint32_t stWhi = stA + ARR_B;
        const uint32_t stWlo = stA + 2 * ARR_B;

        #pragma unroll
        for (int ks = 0; ks < 2; ks++) {
            const uint32_t kadd = (uint32_t)(ks * 32);
            uint32_t a[4][4], bhi[2][4], blo[2][4];
            #pragma unroll
            for (int ni2 = 0; ni2 < 2; ni2++) {
                ldm4(bhi[ni2], stWhi + offB[ni2] + kadd);
                ldm4(blo[ni2], stWlo + offB[ni2] + kadd);
            }
            #pragma unroll
            for (int mi = 0; mi < 4; mi++)
                ldm4(a[mi], stA + offA[mi] + kadd);
            #pragma unroll
            for (int mi = 0; mi < 4; mi++) {
                #pragma unroll
                for (int nf = 0; nf < 4; nf++) {
                    const int ni2 = nf >> 1;
                    const int s   = (nf & 1) * 2;
                    uint32_t bh[2] = { bhi[ni2][s], bhi[ni2][s + 1] };
                    uint32_t bl[2] = { blo[ni2][s], blo[ni2][s + 1] };
                    mma16816h(acc[mi][nf], a[mi], bh);
                    mma16816h(acc[mi][nf], a[mi], bl);
                }
            }
        }
    }

    const int gid = lane >> 2;
    const int tig = lane & 3;
    #pragma unroll
    for (int mi = 0; mi < 4; mi++) {
        #pragma unroll
        for (int nf = 0; nf < 4; nf++) {
            int row = brow + wm * 64 + mi * 16 + gid;
            int col = bcol + wn * 32 + nf * 8 + tig * 2;
            *(float2*)(C + (size_t)row * N + col) =
                make_float2(acc[mi][nf][0], acc[mi][nf][1]);
            *(float2*)(C + (size_t)(row + 8) * N + col) =
                make_float2(acc[mi][nf][2], acc[mi][nf][3]);
        }
    }
}

// =====================================================================
// Depthwise causal conv (width 4) + bias + SiLU; emits fp32 (for scan)
// and fp16 hi/lo (for tensor-core x_proj).
// =====================================================================
__global__ void conv_silu_kernel(const float* __restrict__ xz,
                                 const float* __restrict__ cw,
                                 const float* __restrict__ cb,
                                 float* __restrict__ xconv,
                                 __half* __restrict__ xchi,
                                 __half* __restrict__ xclo)
{
    int idx = blockIdx.x * blockDim.x + threadIdx.x;
    if (idx >= MROWS * DD / 4) return;
    int d4 = idx & (DD / 4 - 1);
    int bt = idx >> 8;
    int t  = bt & (TT - 1);
    int b  = bt >> 11;

    float4 cw0 = ((const float4*)cw)[d4 * 4 + 0];
    float4 cw1 = ((const float4*)cw)[d4 * 4 + 1];
    float4 cw2 = ((const float4*)cw)[d4 * 4 + 2];
    float4 cw3 = ((const float4*)cw)[d4 * 4 + 3];
    float4 acc = ((const float4*)cb)[d4];

    #pragma unroll
    for (int j = 0; j < DCONV; j++) {
        int tt = t - (DCONV - 1) + j;
        if (tt >= 0) {
            float4 xv = *(const float4*)(xz + (size_t)(b * TT + tt) * E2 + d4 * 4);
            float w0 = (&cw0.x)[j], w1 = (&cw1.x)[j], w2 = (&cw2.x)[j], w3 = (&cw3.x)[j];
            acc.x = fmaf(xv.x, w0, acc.x);
            acc.y = fmaf(xv.y, w1, acc.y);
            acc.z = fmaf(xv.z, w2, acc.z);
            acc.w = fmaf(xv.w, w3, acc.w);
        }
    }
    acc.x = acc.x / (1.0f + __expf(-acc.x));
    acc.y = acc.y / (1.0f + __expf(-acc.y));
    acc.z = acc.z / (1.0f + __expf(-acc.z));
    acc.w = acc.w / (1.0f + __expf(-acc.w));
    *(float4*)(xconv + (size_t)bt * DD + d4 * 4) = acc;
    split_one(acc, xchi, xclo, idx);
}

// =====================================================================
// Tensor-core x_proj (3-term fp16): partial[ks][row][e] =
//   sum_{k in chunk ks} xconv[row,k] * Wx[e,k],  e padded to 64.
// Block: 128 rows x 64 e, K=256 per block. grid (32, KSPL).
// 2-stage cp.async, 256 threads, warp tile 64x16.
// =====================================================================
#define XA_B (128*GLDA*2)             // A array bytes  = 10240
#define XW_B (64*GLDA*2)              // W array bytes  = 5120
#define XSTAGE_B (2*XA_B + 2*XW_B)    // Ahi,Alo,Whi,Wlo = 30720
#define XPROJ_SMEM (2*XSTAGE_B)       // 61440

__global__ __launch_bounds__(256, 2) void xproj_mma(
    const __half* __restrict__ Ahi, const __half* __restrict__ Alo,
    const __half* __restrict__ Whi, const __half* __restrict__ Wlo,
    float* __restrict__ pp)
{
    extern __shared__ __align__(16) char dsm[];

    const int tid  = threadIdx.x;
    const int lane = tid & 31;
    const int warp = tid >> 5;
    const int wm   = warp >> 2;          // 0..1 -> 64 rows
    const int wn   = warp & 3;           // 0..3 -> 16 e
    const int brow = blockIdx.x * 128;
    const int kbase = blockIdx.y * KCH;  // K chunk

    float acc[4][2][4];
    #pragma unroll
    for (int i = 0; i < 4; i++)
        #pragma unroll
        for (int j = 0; j < 2; j++)
            #pragma unroll
            for (int k = 0; k < 4; k++) acc[i][j][k] = 0.f;

    const uint32_t sbase = (uint32_t)__cvta_generic_to_shared(dsm);

    const __half* aSrc[2] = { Ahi + (size_t)brow * DD + kbase,
                              Alo + (size_t)brow * DD + kbase };
    const __half* wSrc[2] = { Whi + kbase, Wlo + kbase };

    uint32_t offA[4];
    #pragma unroll
    for (int mi = 0; mi < 4; mi++) {
        int row = wm * 64 + mi * 16 + (lane & 15);
        int ko  = (lane >> 4) * 8;
        offA[mi] = (uint32_t)(row * GLDA + ko) * 2u;
    }
    uint32_t offB;
    {
        int row = wn * 16 + (lane & 7) + ((lane >> 4) << 3);
        int ko  = ((lane >> 3) & 1) * 8;
        offB = (uint32_t)(row * GLDA + ko) * 2u;
    }

    const int NK = KCH / 32;    // 8

    auto load_slab = [&](int slab, int stage) {
        const uint32_t stB = sbase + (uint32_t)stage * XSTAGE_B;
        // A arrays: 512 chunks each, 2/thread
        #pragma unroll
        for (int arr = 0; arr < 2; arr++) {
            const __half* sp = aSrc[arr] + slab * 32;
            #pragma unroll
            for (int j = 0; j < 2; j++) {
                int idx = tid * 2 + j;          // 0..511
                int row = idx >> 2;
                int kc  = idx & 3;
                uint32_t dst = stB + (uint32_t)arr * XA_B + (uint32_t)(row * GLDA + kc * 8) * 2u;
                cpasync16(dst, sp + (size_t)row * DD + kc * 8);
            }
        }
        // W arrays: 256 chunks each, 1/thread
        #pragma unroll
        for (int arr = 0; arr < 2; arr++) {
            const __half* sp = wSrc[arr] + slab * 32;
            int row = tid >> 2;                 // 0..63
            int kc  = tid & 3;
            uint32_t dst = stB + 2u * XA_B + (uint32_t)arr * XW_B + (uint32_t)(row * GLDA + kc * 8) * 2u;
            cpasync16(dst, sp + (size_t)row * DD + kc * 8);
        }
        asm volatile("cp.async.commit_group;");
    };

    load_slab(0, 0);
    load_slab(1, 1);

    for (int kt = 0; kt < NK; kt++) {
        const int stage = kt & 1;
        if (kt < NK - 1) asm volatile("cp.async.wait_group 1;");
        else             asm volatile("cp.async.wait_group 0;");
        __syncthreads();

        const uint32_t stAhi = sbase + (uint32_t)stage * XSTAGE_B;
        const uint32_t stAlo = stAhi + XA_B;
        const uint32_t stWhi = stAhi + 2 * XA_B;
        const uint32_t stWlo = stWhi + XW_B;

        #pragma unroll
        for (int ks = 0; ks < 2; ks++) {
            const uint32_t kadd = (uint32_t)(ks * 32);
            uint32_t ahi[4][4], alo[4][4], bhi[4], blo[4];
            ldm4(bhi, stWhi + offB + kadd);
            ldm4(blo, stWlo + offB + kadd);
            #pragma unroll
            for (int mi = 0; mi < 4; mi++) {
                ldm4(ahi[mi], stAhi + offA[mi] + kadd);
                ldm4(alo[mi], stAlo + offA[mi] + kadd);
            }
            #pragma unroll
            for (int mi = 0; mi < 4; mi++) {
                #pragma unroll
                for (int nf = 0; nf < 2; nf++) {
                    uint32_t bh[2] = { bhi[nf * 2], bhi[nf * 2 + 1] };
                    uint32_t bl[2] = { blo[nf * 2], blo[nf * 2 + 1] };
                    mma16816h(acc[mi][nf], ahi[mi], bh);
                    mma16816h(acc[mi][nf], alo[mi], bh);
                    mma16816h(acc[mi][nf], ahi[mi], bl);
                }
            }
        }
        // next-next slab load AFTER compute: stage reuse is safe because the
        // __syncthreads at top of next iter orders it; issue here to overlap.
        if (kt + 2 < NK) load_slab(kt + 2, stage);
    }

    float* base = pp + (size_t)blockIdx.y * MROWS * NPAR;
    const int gid = lane >> 2;
    const int tig = lane & 3;
    #pragma unroll
    for (int mi = 0; mi < 4; mi++) {
        #pragma unroll
        for (int nf = 0; nf < 2; nf++) {
            int row = brow + wm * 64 + mi * 16 + gid;
            int e   = wn * 16 + nf * 8 + tig * 2;
            if (e < NPAR) {
                float* r0 = base + (size_t)row * NPAR + e;
                float* r1 = base + (size_t)(row + 8) * NPAR + e;
                r0[0] = acc[mi][nf][0];
                r1[0] = acc[mi][nf][2];
                if (e + 1 < NPAR) {
                    r0[1] = acc[mi][nf][1];
                    r1[1] = acc[mi][nf][3];
                }
            }
        }
    }
}

// =====================================================================
// Scan pass A. Chunk params staged in padded smem, summing the KSPL
// partials during staging. Fast exp-chain path when A_log = log(1..N).
// =====================================================================
#define SPQ (CHL*NPAR/4)              // 528 float4 per chunk
#define PSTR ((size_t)MROWS*NPAR/4)   // partial stride in float4

__global__ __launch_bounds__(128) void scanA_kernel(const float* __restrict__ params,
                                                    const float* __restrict__ xconv,
                                                    const float* __restrict__ dtw,
                                                    const float* __restrict__ dtb,
                                                    const float* __restrict__ A_log,
                                                    float* __restrict__ Pout,
                                                    float* __restrict__ hend)
{
    __shared__ float sp[CHL][36];
    const int dg = blockIdx.x & 7;
    const int c  = (blockIdx.x >> 3) & (NCH - 1);
    const int b  = blockIdx.x >> 8;
    const int d  = dg * 128 + threadIdx.x;
    const size_t rowbase = (size_t)b * TT + (size_t)c * CHL;

    {
        const float4* src = (const float4*)(params + rowbase * NPAR);
        for (int i = threadIdx.x; i < SPQ; i += 128) {
            float4 v0 = src[i];
            float4 v1 = src[i + PSTR];
            float4 v2 = src[i + 2 * PSTR];
            float4 v3 = src[i + 3 * PSTR];
            float4 v = make_float4((v0.x + v1.x) + (v2.x + v3.x),
                                   (v0.y + v1.y) + (v2.y + v3.y),
                                   (v0.z + v1.z) + (v2.z + v3.z),
                                   (v0.w + v1.w) + (v2.w + v3.w));
            int e = i * 4;
            #pragma unroll
            for (int j = 0; j < 4; j++) {
                int ee = e + j;
                sp[ee / NPAR][ee % NPAR] = (&v.x)[j];
            }
        }
    }

    float a[NN];
    #pragma unroll
    for (int n = 0; n < NN; n++)
        a[n] = -expf(A_log[(size_t)d * NN + n]);
    const float w    = dtw[d];
    const float bias = dtb[d];

    bool fast = true;
    #pragma unroll
    for (int n = 1; n < NN; n++)
        fast = fast && (fabsf(a[n] - (float)(n + 1) * a[0]) <= 1e-4f * fabsf(a[n]) + 1e-12f);

    float h[NN], P[NN];
    #pragma unroll
    for (int n = 0; n < NN; n++) { h[n] = 0.f; P[n] = 1.f; }

    __syncthreads();

    if (fast) {
        const float a0 = a[0];
        for (int t = 0; t < CHL; t++) {
            float pv[16];
            *(float4*)&pv[0]  = *(const float4*)&sp[t][0];
            *(float4*)&pv[4]  = *(const float4*)&sp[t][4];
            *(float4*)&pv[8]  = *(const float4*)&sp[t][8];
            *(float4*)&pv[12] = *(const float4*)&sp[t][12];
            float v  = fmaf(sp[t][32], w, bias);
            float dt = (v > 20.f) ? v : __logf(1.0f + __expf(v));
            float dtx = dt * xconv[(rowbase + t) * DD + d];
            float q = __expf(dt * a0);
            float e = q;
            #pragma unroll
            for (int n = 0; n < NN; n++) {
                h[n] = fmaf(e, h[n], dtx * pv[n]);
                P[n] *= e;
                e *= q;
            }
        }
    } else {
        for (int t = 0; t < CHL; t++) {
            float pv[16];
            *(float4*)&pv[0]  = *(const float4*)&sp[t][0];
            *(float4*)&pv[4]  = *(const float4*)&sp[t][4];
            *(float4*)&pv[8]  = *(const float4*)&sp[t][8];
            *(float4*)&pv[12] = *(const float4*)&sp[t][12];
            float v  = fmaf(sp[t][32], w, bias);
            float dt = (v > 20.f) ? v : __logf(1.0f + __expf(v));
            float dtx = dt * xconv[(rowbase + t) * DD + d];
            #pragma unroll
            for (int n = 0; n < NN; n++) {
                float e = __expf(dt * a[n]);
                h[n] = fmaf(e, h[n], dtx * pv[n]);
                P[n] *= e;
            }
        }
    }
    const size_t o = ((size_t)(b * NCH + c) * NN) * DD + d;
    #pragma unroll
    for (int n = 0; n < NN; n++) {
        hend[o + (size_t)n * DD] = h[n];
        Pout[o + (size_t)n * DD] = P[n];
    }
}

// =====================================================================
// Pass B: sequential chunk combine.
// =====================================================================
__global__ void scanB_kernel(const float* __restrict__ P,
                             const float* __restrict__ hend,
                             float* __restrict__ hini)
{
    int gid = blockIdx.x * blockDim.x + threadIdx.x;
    if (gid >= BB * DD) return;
    int d = gid & (DD - 1);
    int b = gid >> 10;

    float h[NN];
    #pragma unroll
    for (int n = 0; n < NN; n++) h[n] = 0.f;

    for (int c = 0; c < NCH; c++) {
        const size_t o = ((size_t)(b * NCH + c) * NN) * DD + d;
        #pragma unroll
        for (int n = 0; n < NN; n++) {
            hini[o + (size_t)n * DD] = h[n];
            h[n] = fmaf(P[o + (size_t)n * DD], h[n], hend[o + (size_t)n * DD]);
        }
    }
}

// =====================================================================
// Pass C: re-run chunks from h_init; emit y=(h·C)*silu(z) as fp16.
// =====================================================================
__global__ __launch_bounds__(128) void scanC_kernel(const float* __restrict__ params,
                                                    const float* __restrict__ xconv,
                                                    const float* __restrict__ xz,
                                                    const float* __restrict__ dtw,
                                                    const float* __restrict__ dtb,
                                                    const float* __restrict__ A_log,
                                                    const float* __restrict__ hini,
                                                    __half* __restrict__ yh)
{
    __shared__ float sp[CHL][36];
    const int dg = blockIdx.x & 7;
    const int c  = (blockIdx.x >> 3) & (NCH - 1);
    const int b  = blockIdx.x >> 8;
    const int d  = dg * 128 + threadIdx.x;
    const size_t rowbase = (size_t)b * TT + (size_t)c * CHL;

    {
        const float4* src = (const float4*)(params + rowbase * NPAR);
        for (int i = threadIdx.x; i < SPQ; i += 128) {
            float4 v0 = src[i];
            float4 v1 = src[i + PSTR];
            float4 v2 = src[i + 2 * PSTR];
            float4 v3 = src[i + 3 * PSTR];
            float4 v = make_float4((v0.x + v1.x) + (v2.x + v3.x),
                                   (v0.y + v1.y) + (v2.y + v3.y),
                                   (v0.z + v1.z) + (v2.z + v3.z),
                                   (v0.w + v1.w) + (v2.w + v3.w));
            int e = i * 4;
            #pragma unroll
            for (int j = 0; j < 4; j++) {
                int ee = e + j;
                sp[ee / NPAR][ee % NPAR] = (&v.x)[j];
            }
        }
    }

    float a[NN];
    #pragma unroll
    for (int n = 0; n < NN; n++)
        a[n] = -expf(A_log[(size_t)d * NN + n]);
    const float w    = dtw[d];
    const float bias = dtb[d];

    bool fast = true;
    #pragma unroll
    for (int n = 1; n < NN; n++)
        fast = fast && (fabsf(a[n] - (float)(n + 1) * a[0]) <= 1e-4f * fabsf(a[n]) + 1e-12f);

    float h[NN];
    const size_t o = ((size_t)(b * NCH + c) * NN) * DD + d;
    #pragma unroll
    for (int n = 0; n < NN; n++) h[n] = hini[o + (size_t)n * DD];

    __syncthreads();

    if (fast) {
        const float a0 = a[0];
        for (int t = 0; t < CHL; t++) {
            const size_t r = rowbase + t;
            float pv[16], cv[16];
            *(float4*)&pv[0]  = *(const float4*)&sp[t][0];
            *(float4*)&pv[4]  = *(const float4*)&sp[t][4];
            *(float4*)&pv[8]  = *(const float4*)&sp[t][8];
            *(float4*)&pv[12] = *(const float4*)&sp[t][12];
            *(float4*)&cv[0]  = *(const float4*)&sp[t][16];
            *(float4*)&cv[4]  = *(const float4*)&sp[t][20];
            *(float4*)&cv[8]  = *(const float4*)&sp[t][24];
            *(float4*)&cv[12] = *(const float4*)&sp[t][28];
            float v  = fmaf(sp[t][32], w, bias);
            float dt = (v > 20.f) ? v : __logf(1.0f + __expf(v));
            float dtx = dt * xconv[r * DD + d];
            float zv  = xz[r * E2 + DD + d];
            float q = __expf(dt * a0);
            float e = q;
            float yv = 0.f;
            #pragma unroll
            for (int n = 0; n < NN; n++) {
                h[n] = fmaf(e, h[n], dtx * pv[n]);
                yv = fmaf(h[n], cv[n], yv);
                e *= q;
            }
            float sil = zv / (1.0f + __expf(-zv));
            yh[r * DD + d] = __float2half_rn(yv * sil);
        }
    } else {
        for (int t = 0; t < CHL; t++) {
            const size_t r = rowbase + t;
            float pv[16], cv[16];
            *(float4*)&pv[0]  = *(const float4*)&sp[t][0];
            *(float4*)&pv[4]  = *(const float4*)&sp[t][4];
            *(float4*)&pv[8]  = *(const float4*)&sp[t][8];
            *(float4*)&pv[12] = *(const float4*)&sp[t][12];
            *(float4*)&cv[0]  = *(const float4*)&sp[t][16];
            *(float4*)&cv[4]  = *(const float4*)&sp[t][20];
            *(float4*)&cv[8]  = *(const float4*)&sp[t][24];
            *(float4*)&cv[12] = *(const float4*)&sp[t][28];
            float v  = fmaf(sp[t][32], w, bias);
            float dt = (v > 20.f) ? v : __logf(1.0f + __expf(v));
            float dtx = dt * xconv[r * DD + d];
            float zv  = xz[r * E2 + DD + d];
            float yv = 0.f;
            #pragma unroll
            for (int n = 0; n < NN; n++) {
                float e = __expf(dt * a[n]);
                h[n] = fmaf(e, h[n], dtx * pv[n]);
                yv = fmaf(h[n], cv[n], yv);
            }
            float sil = zv / (1.0f + __expf(-zv));
            yh[r * DD + d] = __float2half_rn(yv * sil);
        }
    }
}

// =====================================================================
// launch
// =====================================================================
extern "C" void kernel_launch(void* const* d_in, const int* in_sizes, int n_in,
                              void* d_out, int out_size)
{
    const float* x         = (const float*)d_in[0];
    const float* in_proj_w = (const float*)d_in[1];
    const float* conv_w    = (const float*)d_in[2];
    const float* conv_b    = (const float*)d_in[3];
    const float* x_proj_w  = (const float*)d_in[4];
    const float* dt_proj_w = (const float*)d_in[5];
    const float* dt_proj_b = (const float*)d_in[6];
    const float* A_log     = (const float*)d_in[7];
    const float* out_proj_w= (const float*)d_in[8];
    float* out = (float*)d_out;

    float *xz, *xconv, *params, *P, *hend, *hini;
    __half *xh, *w1hi, *w1lo, *w2hi, *w2lo, *yh, *xchi, *xclo, *wxhi, *wxlo;
    cudaGetSymbolAddress((void**)&xz,     g_xz);
    cudaGetSymbolAddress((void**)&xconv,  g_xconv);
    cudaGetSymbolAddress((void**)&params, g_params);
    cudaGetSymbolAddress((void**)&P,      g_P);
    cudaGetSymbolAddress((void**)&hend,   g_hend);
    cudaGetSymbolAddress((void**)&hini,   g_hini);
    cudaGetSymbolAddress((void**)&xh,     g_xh);
    cudaGetSymbolAddress((void**)&w1hi,   g_w1hi);
    cudaGetSymbolAddress((void**)&w1lo,   g_w1lo);
    cudaGetSymbolAddress((void**)&w2hi,   g_w2hi);
    cudaGetSymbolAddress((void**)&w2lo,   g_w2lo);
    cudaGetSymbolAddress((void**)&yh,     g_yh);
    cudaGetSymbolAddress((void**)&xchi,   g_xchi);
    cudaGetSymbolAddress((void**)&xclo,   g_xclo);
    cudaGetSymbolAddress((void**)&wxhi,   g_wxhi);
    cudaGetSymbolAddress((void**)&wxlo,   g_wxlo);

    cudaFuncSetAttribute(gemm_fp16_2t,
                         cudaFuncAttributeMaxDynamicSharedMemorySize, GEMM_SMEM);
    cudaFuncSetAttribute(xproj_mma,
                         cudaFuncAttributeMaxDynamicSharedMemorySize, XPROJ_SMEM);

    // 0) merged precision prep
    prep_kernel<<<(N_PREP + 255)/256, 256>>>(x, in_proj_w, out_proj_w, x_proj_w,
                                             xh, w1hi, w1lo, w2hi, w2lo, wxhi, wxlo);

    // 1) in_proj
    {
        dim3 grid(E2 / 128, MROWS / 128);
        gemm_fp16_2t<<<grid, 256, GEMM_SMEM>>>(xh, w1hi, w1lo, xz, MROWS, E2, DD);
    }
    // 2) depthwise conv + SiLU (fp32 + fp16 hi/lo outputs)
    conv_silu_kernel<<<(MROWS*DD/4 + 255)/256, 256>>>(xz, conv_w, conv_b,
                                                      xconv, xchi, xclo);
    // 3) x_proj (tensor-core, 3-term, K-split)
    {
        dim3 grid(MROWS / 128, KSPL);
        xproj_mma<<<grid, 256, XPROJ_SMEM>>>(xchi, xclo, wxhi, wxlo, params);
    }
    // 4) chunked selective scan
    scanA_kernel<<<BB * NCH * (DD/128), 128>>>(params, xconv, dt_proj_w, dt_proj_b, A_log, P, hend);
    scanB_kernel<<<(BB*DD + 255)/256, 256>>>(P, hend, hini);
    scanC_kernel<<<BB * NCH * (DD/128), 128>>>(params, xconv, xz, dt_proj_w, dt_proj_b, A_log, hini, yh);
    // 5) out_proj
    {
        dim3 grid(DD / 128, MROWS / 128);
        gemm_fp16_2t<<<grid, 256, GEMM_SMEM>>>(yh, w2hi, w2lo, out, MROWS, DD, DD);
    }
}